// round 1
// baseline (speedup 1.0000x reference)
#include <cuda_runtime.h>
#include <cuda_bf16.h>
#include <math.h>

// Problem constants
#define NSEQ 2048
#define DIM  2048
#define HEADS 32
#define KVHEADS 4
#define HD 64           // head dim
#define KVDIM (KVHEADS*HD)   // 256
#define REP (HEADS/KVHEADS)  // 8
#define SCALE 0.125f         // 1/sqrt(64)

// ---------------- scratch (device globals; no allocation allowed) ----------------
__device__ float g_q[NSEQ * DIM];     // 16 MB
__device__ float g_k[NSEQ * KVDIM];   //  2 MB
__device__ float g_v[NSEQ * KVDIM];   //  2 MB
__device__ float g_y[NSEQ * DIM];     // 16 MB

// ---------------- NT GEMM: C[m][n] = sum_k A[m][k] * B[n][k] ----------------
template<int BM, int BN, int BK, int TM, int TN>
__global__ void __launch_bounds__((BM/TM)*(BN/TN))
gemm_nt(const float* __restrict__ A, const float* __restrict__ B,
        float* __restrict__ C, int M, int N, int K)
{
    constexpr int THREADS = (BM/TM)*(BN/TN);
    __shared__ float As[BK][BM + 4];
    __shared__ float Bs[BK][BN + 4];

    const int tid = threadIdx.x;
    const int tx = tid % (BN/TN);
    const int ty = tid / (BN/TN);
    const int m0 = blockIdx.y * BM;
    const int n0 = blockIdx.x * BN;

    float acc[TM][TN];
    #pragma unroll
    for (int i = 0; i < TM; i++)
        #pragma unroll
        for (int j = 0; j < TN; j++) acc[i][j] = 0.f;

    for (int k0 = 0; k0 < K; k0 += BK) {
        // load A tile (BM x BK), store transposed
        constexpr int A4 = BM * BK / 4;
        #pragma unroll
        for (int i = tid; i < A4; i += THREADS) {
            int row = i / (BK/4), kq = i % (BK/4);
            float4 val = *(const float4*)&A[(size_t)(m0 + row) * K + k0 + kq*4];
            As[kq*4+0][row] = val.x; As[kq*4+1][row] = val.y;
            As[kq*4+2][row] = val.z; As[kq*4+3][row] = val.w;
        }
        // load B tile (BN x BK), store transposed
        constexpr int B4 = BN * BK / 4;
        #pragma unroll
        for (int i = tid; i < B4; i += THREADS) {
            int row = i / (BK/4), kq = i % (BK/4);
            float4 val = *(const float4*)&B[(size_t)(n0 + row) * K + k0 + kq*4];
            Bs[kq*4+0][row] = val.x; Bs[kq*4+1][row] = val.y;
            Bs[kq*4+2][row] = val.z; Bs[kq*4+3][row] = val.w;
        }
        __syncthreads();

        #pragma unroll
        for (int kk = 0; kk < BK; kk++) {
            float a[TM], b[TN];
            #pragma unroll
            for (int i = 0; i < TM; i++) a[i] = As[kk][ty*TM + i];
            #pragma unroll
            for (int j = 0; j < TN; j++) b[j] = Bs[kk][tx*TN + j];
            #pragma unroll
            for (int i = 0; i < TM; i++)
                #pragma unroll
                for (int j = 0; j < TN; j++)
                    acc[i][j] += a[i] * b[j];
        }
        __syncthreads();
    }

    #pragma unroll
    for (int i = 0; i < TM; i++) {
        #pragma unroll
        for (int j = 0; j < TN; j++) {
            C[(size_t)(m0 + ty*TM + i) * N + n0 + tx*TN + j] = acc[i][j];
        }
    }
}

// ---------------- RoPE (in-place) ----------------
// layout: t[n][h*64 + d]; pair (j, j+32): out[j] = x0*c - x1*s ; out[j+32] = x1*c + x0*s
__global__ void rope_kernel(float* __restrict__ t, const float* __restrict__ cosd,
                            const float* __restrict__ sind, int nheads, int rowstride)
{
    int idx = blockIdx.x * blockDim.x + threadIdx.x;
    int total = NSEQ * nheads * 32;
    if (idx >= total) return;
    int j = idx & 31;
    int h = (idx >> 5) % nheads;
    int n = idx / (32 * nheads);
    float c0 = cosd[n*HD + j],      s0 = sind[n*HD + j];
    float c1 = cosd[n*HD + 32 + j], s1 = sind[n*HD + 32 + j];
    float* p = t + (size_t)n * rowstride + h * HD;
    float x0 = p[j], x1 = p[j + 32];
    p[j]      = x0 * c0 - x1 * s0;
    p[j + 32] = x1 * c1 + x0 * s1;
}

// ---------------- causal flash attention, fp32 ----------------
// grid (16 qblocks of 128 rows, 32 heads), 128 threads; thread owns one query row.
__global__ void __launch_bounds__(128)
attn_kernel(const float* __restrict__ Q, const float* __restrict__ Kp,
            const float* __restrict__ Vp, float* __restrict__ Y)
{
    __shared__ float4 Ks[32][16];
    __shared__ float4 Vs[32][16];

    const int h = blockIdx.y;
    const int kvh = h / REP;
    const int row = blockIdx.x * 128 + threadIdx.x;

    float4 qr[16];
    const float4* qrow = (const float4*)(Q + (size_t)row * DIM + h * HD);
    #pragma unroll
    for (int i = 0; i < 16; i++) qr[i] = qrow[i];

    float mval = -1e30f, l = 0.f;
    float4 acc[16];
    #pragma unroll
    for (int i = 0; i < 16; i++) acc[i] = make_float4(0.f, 0.f, 0.f, 0.f);

    const int s_end = blockIdx.x * 128 + 128;
    for (int s0 = 0; s0 < s_end; s0 += 32) {
        // cooperative load of 32 K rows and 32 V rows (64 floats each)
        #pragma unroll
        for (int i = 0; i < 4; i++) {
            int li = threadIdx.x + i * 128;  // 0..511
            int r = li >> 4, c = li & 15;
            Ks[r][c] = *(const float4*)(Kp + (size_t)(s0 + r) * KVDIM + kvh * HD + c * 4);
            Vs[r][c] = *(const float4*)(Vp + (size_t)(s0 + r) * KVDIM + kvh * HD + c * 4);
        }
        __syncthreads();

        float sc[32];
        #pragma unroll
        for (int s = 0; s < 32; s++) sc[s] = 0.f;

        // scores: 64-d dot products against 32 keys (smem broadcast reads)
        #pragma unroll 4
        for (int c = 0; c < 16; c++) {
            float4 q4 = qr[c];
            #pragma unroll
            for (int s = 0; s < 32; s++) {
                float4 k4 = Ks[s][c];
                sc[s] += q4.x * k4.x + q4.y * k4.y + q4.z * k4.z + q4.w * k4.w;
            }
        }

        // mask + online softmax
        float tmax = mval;
        #pragma unroll
        for (int s = 0; s < 32; s++) {
            float v = (s0 + s <= row) ? sc[s] * SCALE : -1e30f;
            sc[s] = v;
            tmax = fmaxf(tmax, v);
        }
        float corr = __expf(mval - tmax);
        l *= corr;
        #pragma unroll
        for (int i = 0; i < 16; i++) {
            acc[i].x *= corr; acc[i].y *= corr; acc[i].z *= corr; acc[i].w *= corr;
        }
        #pragma unroll
        for (int s = 0; s < 32; s++) {
            float p = __expf(sc[s] - tmax);
            sc[s] = p;
            l += p;
        }
        // acc += P @ V
        #pragma unroll 4
        for (int s = 0; s < 32; s++) {
            float p = sc[s];
            #pragma unroll
            for (int c = 0; c < 16; c++) {
                float4 v4 = Vs[s][c];
                acc[c].x += p * v4.x; acc[c].y += p * v4.y;
                acc[c].z += p * v4.z; acc[c].w += p * v4.w;
            }
        }
        mval = tmax;
        __syncthreads();
    }

    float inv = 1.f / l;
    float4* yrow = (float4*)(Y + (size_t)row * DIM + h * HD);
    #pragma unroll
    for (int c = 0; c < 16; c++) {
        float4 a = acc[c];
        a.x *= inv; a.y *= inv; a.z *= inv; a.w *= inv;
        yrow[c] = a;
    }
}

// ---------------- launch ----------------
extern "C" void kernel_launch(void* const* d_in, const int* in_sizes, int n_in,
                              void* d_out, int out_size)
{
    const float* x   = (const float*)d_in[0];
    const float* Wq  = (const float*)d_in[1];
    const float* Wk  = (const float*)d_in[2];
    const float* Wv  = (const float*)d_in[3];
    const float* Wo  = (const float*)d_in[4];
    const float* cosd= (const float*)d_in[5];
    const float* sind= (const float*)d_in[6];
    float* out = (float*)d_out;

    float *qp, *kp, *vp, *yp;
    cudaGetSymbolAddress((void**)&qp, g_q);
    cudaGetSymbolAddress((void**)&kp, g_k);
    cudaGetSymbolAddress((void**)&vp, g_v);
    cudaGetSymbolAddress((void**)&yp, g_y);

    // Q projection: [2048,2048] = x @ Wq^T
    gemm_nt<128,128,16,8,8><<<dim3(DIM/128, NSEQ/128), 256>>>(x, Wq, qp, NSEQ, DIM, DIM);
    // K,V projections: [2048,256]
    gemm_nt<64,64,16,4,4><<<dim3(KVDIM/64, NSEQ/64), 256>>>(x, Wk, kp, NSEQ, KVDIM, DIM);
    gemm_nt<64,64,16,4,4><<<dim3(KVDIM/64, NSEQ/64), 256>>>(x, Wv, vp, NSEQ, KVDIM, DIM);

    // RoPE
    {
        int totq = NSEQ * HEADS * 32;
        rope_kernel<<<(totq + 255) / 256, 256>>>(qp, cosd, sind, HEADS, DIM);
        int totk = NSEQ * KVHEADS * 32;
        rope_kernel<<<(totk + 255) / 256, 256>>>(kp, cosd, sind, KVHEADS, KVDIM);
    }

    // attention
    attn_kernel<<<dim3(NSEQ/128, HEADS), 128>>>(qp, kp, vp, yp);

    // output projection: out = y @ Wo^T
    gemm_nt<128,128,16,8,8><<<dim3(DIM/128, NSEQ/128), 256>>>(yp, Wo, out, NSEQ, DIM, DIM);
}

// round 2
// speedup vs baseline: 1.0595x; 1.0595x over previous
#include <cuda_runtime.h>
#include <cuda_bf16.h>
#include <math.h>
#include <stdint.h>

// Problem constants
#define NSEQ 2048
#define DIM  2048
#define HEADS 32
#define KVHEADS 4
#define HD 64
#define KVDIM (KVHEADS*HD)   // 256
#define REP (HEADS/KVHEADS)  // 8
#define SCALE 0.125f

// ---------------- scratch ----------------
__device__ float g_q[NSEQ * DIM];
__device__ float g_k[NSEQ * KVDIM];
__device__ float g_v[NSEQ * KVDIM];
__device__ float g_y[NSEQ * DIM];

// ---------------- tf32 helpers ----------------
__device__ __forceinline__ uint32_t f2tf(float x) {
    uint32_t r;
    asm("cvt.rna.tf32.f32 %0, %1;" : "=r"(r) : "f"(x));
    return r;
}

__device__ __forceinline__ void mma_tf32(float* d, const uint32_t* a, const uint32_t* b) {
    asm volatile(
        "mma.sync.aligned.m16n8k8.row.col.f32.tf32.tf32.f32 "
        "{%0,%1,%2,%3}, {%4,%5,%6,%7}, {%8,%9}, {%0,%1,%2,%3};"
        : "+f"(d[0]), "+f"(d[1]), "+f"(d[2]), "+f"(d[3])
        : "r"(a[0]), "r"(a[1]), "r"(a[2]), "r"(a[3]), "r"(b[0]), "r"(b[1]));
}

// ---------------- 3xTF32 NT GEMM: C[m][n] = sum_k A[m][k]*B[n][k] ----------------
// Warp tile 64x32 (4 m-frags x 4 n-frags of m16n8k8), split-precision hi/lo in smem.
template<int BM, int BN>
__global__ void __launch_bounds__(32*(BM/64)*(BN/32))
gemm_tf32(const float* __restrict__ A, const float* __restrict__ B,
          float* __restrict__ C, int M, int N, int K)
{
    constexpr int BK = 32;
    constexpr int LDSW = BK + 4;            // padded row (u32)
    constexpr int WN_TILES = BN / 32;
    constexpr int WM_TILES = BM / 64;
    constexpr int WARPS = WM_TILES * WN_TILES;
    constexpr int THREADS = 32 * WARPS;
    constexpr int SA = BM * LDSW;
    constexpr int SB = BN * LDSW;

    extern __shared__ uint32_t sm[];
    uint32_t* Ah = sm;
    uint32_t* Al = sm + SA;
    uint32_t* Bh = sm + 2 * SA;
    uint32_t* Bl = sm + 2 * SA + SB;

    const int tid  = threadIdx.x;
    const int lane = tid & 31;
    const int warp = tid >> 5;
    const int wm   = warp / WN_TILES;
    const int wn   = warp % WN_TILES;
    const int m0   = blockIdx.y * BM;
    const int n0   = blockIdx.x * BN;

    float acc[4][4][4];
    #pragma unroll
    for (int i = 0; i < 4; i++)
        #pragma unroll
        for (int j = 0; j < 4; j++)
            #pragma unroll
            for (int r = 0; r < 4; r++) acc[i][j][r] = 0.f;

    for (int k0 = 0; k0 < K; k0 += BK) {
        // ---- load + split A tile (BM x BK) ----
        #pragma unroll
        for (int i = tid; i < BM * (BK / 4); i += THREADS) {
            int row = i / (BK / 4);
            int kq  = (i % (BK / 4)) * 4;
            float4 v = *(const float4*)&A[(size_t)(m0 + row) * K + k0 + kq];
            float xs[4] = {v.x, v.y, v.z, v.w};
            #pragma unroll
            for (int e = 0; e < 4; e++) {
                uint32_t hi = f2tf(xs[e]);
                uint32_t lo = f2tf(xs[e] - __uint_as_float(hi));
                Ah[row * LDSW + kq + e] = hi;
                Al[row * LDSW + kq + e] = lo;
            }
        }
        // ---- load + split B tile (BN x BK) ----
        #pragma unroll
        for (int i = tid; i < BN * (BK / 4); i += THREADS) {
            int row = i / (BK / 4);
            int kq  = (i % (BK / 4)) * 4;
            float4 v = *(const float4*)&B[(size_t)(n0 + row) * K + k0 + kq];
            float xs[4] = {v.x, v.y, v.z, v.w};
            #pragma unroll
            for (int e = 0; e < 4; e++) {
                uint32_t hi = f2tf(xs[e]);
                uint32_t lo = f2tf(xs[e] - __uint_as_float(hi));
                Bh[row * LDSW + kq + e] = hi;
                Bl[row * LDSW + kq + e] = lo;
            }
        }
        __syncthreads();

        #pragma unroll
        for (int ks = 0; ks < BK / 8; ks++) {
            uint32_t ah[4][4], al[4][4], bh[4][2], bl[4][2];
            const int c0 = ks * 8 + (lane & 3);
            #pragma unroll
            for (int i = 0; i < 4; i++) {
                int r0 = wm * 64 + i * 16 + (lane >> 2);
                ah[i][0] = Ah[r0 * LDSW + c0];
                ah[i][1] = Ah[(r0 + 8) * LDSW + c0];
                ah[i][2] = Ah[r0 * LDSW + c0 + 4];
                ah[i][3] = Ah[(r0 + 8) * LDSW + c0 + 4];
                al[i][0] = Al[r0 * LDSW + c0];
                al[i][1] = Al[(r0 + 8) * LDSW + c0];
                al[i][2] = Al[r0 * LDSW + c0 + 4];
                al[i][3] = Al[(r0 + 8) * LDSW + c0 + 4];
            }
            #pragma unroll
            for (int j = 0; j < 4; j++) {
                int nr = wn * 32 + j * 8 + (lane >> 2);
                bh[j][0] = Bh[nr * LDSW + c0];
                bh[j][1] = Bh[nr * LDSW + c0 + 4];
                bl[j][0] = Bl[nr * LDSW + c0];
                bl[j][1] = Bl[nr * LDSW + c0 + 4];
            }
            #pragma unroll
            for (int i = 0; i < 4; i++)
                #pragma unroll
                for (int j = 0; j < 4; j++) {
                    mma_tf32(acc[i][j], ah[i], bh[j]);
                    mma_tf32(acc[i][j], ah[i], bl[j]);
                    mma_tf32(acc[i][j], al[i], bh[j]);
                }
        }
        __syncthreads();
    }

    // ---- epilogue ----
    #pragma unroll
    for (int i = 0; i < 4; i++) {
        #pragma unroll
        for (int j = 0; j < 4; j++) {
            int row = m0 + wm * 64 + i * 16 + (lane >> 2);
            int col = n0 + wn * 32 + j * 8 + (lane & 3) * 2;
            float2 v01 = make_float2(acc[i][j][0], acc[i][j][1]);
            float2 v23 = make_float2(acc[i][j][2], acc[i][j][3]);
            *(float2*)&C[(size_t)row * N + col]       = v01;
            *(float2*)&C[(size_t)(row + 8) * N + col] = v23;
        }
    }
}

// ---------------- RoPE (in-place) ----------------
__global__ void rope_kernel(float* __restrict__ t, const float* __restrict__ cosd,
                            const float* __restrict__ sind, int nheads, int rowstride)
{
    int idx = blockIdx.x * blockDim.x + threadIdx.x;
    int total = NSEQ * nheads * 32;
    if (idx >= total) return;
    int j = idx & 31;
    int h = (idx >> 5) % nheads;
    int n = idx / (32 * nheads);
    float c0 = cosd[n*HD + j],      s0 = sind[n*HD + j];
    float c1 = cosd[n*HD + 32 + j], s1 = sind[n*HD + 32 + j];
    float* p = t + (size_t)n * rowstride + h * HD;
    float x0 = p[j], x1 = p[j + 32];
    p[j]      = x0 * c0 - x1 * s0;
    p[j + 32] = x1 * c1 + x0 * s1;
}

// ---------------- causal flash attention, fp32 ----------------
__global__ void __launch_bounds__(128)
attn_kernel(const float* __restrict__ Q, const float* __restrict__ Kp,
            const float* __restrict__ Vp, float* __restrict__ Y)
{
    __shared__ float4 Ks[32][16];
    __shared__ float4 Vs[32][16];

    const int h = blockIdx.y;
    const int kvh = h / REP;
    const int row = blockIdx.x * 128 + threadIdx.x;

    float4 qr[16];
    const float4* qrow = (const float4*)(Q + (size_t)row * DIM + h * HD);
    #pragma unroll
    for (int i = 0; i < 16; i++) qr[i] = qrow[i];

    float mval = -1e30f, l = 0.f;
    float4 acc[16];
    #pragma unroll
    for (int i = 0; i < 16; i++) acc[i] = make_float4(0.f, 0.f, 0.f, 0.f);

    const int s_end = blockIdx.x * 128 + 128;
    for (int s0 = 0; s0 < s_end; s0 += 32) {
        #pragma unroll
        for (int i = 0; i < 4; i++) {
            int li = threadIdx.x + i * 128;
            int r = li >> 4, c = li & 15;
            Ks[r][c] = *(const float4*)(Kp + (size_t)(s0 + r) * KVDIM + kvh * HD + c * 4);
            Vs[r][c] = *(const float4*)(Vp + (size_t)(s0 + r) * KVDIM + kvh * HD + c * 4);
        }
        __syncthreads();

        float sc[32];
        #pragma unroll
        for (int s = 0; s < 32; s++) sc[s] = 0.f;

        #pragma unroll 4
        for (int c = 0; c < 16; c++) {
            float4 q4 = qr[c];
            #pragma unroll
            for (int s = 0; s < 32; s++) {
                float4 k4 = Ks[s][c];
                sc[s] += q4.x * k4.x + q4.y * k4.y + q4.z * k4.z + q4.w * k4.w;
            }
        }

        float tmax = mval;
        #pragma unroll
        for (int s = 0; s < 32; s++) {
            float v = (s0 + s <= row) ? sc[s] * SCALE : -1e30f;
            sc[s] = v;
            tmax = fmaxf(tmax, v);
        }
        float corr = __expf(mval - tmax);
        l *= corr;
        #pragma unroll
        for (int i = 0; i < 16; i++) {
            acc[i].x *= corr; acc[i].y *= corr; acc[i].z *= corr; acc[i].w *= corr;
        }
        #pragma unroll
        for (int s = 0; s < 32; s++) {
            float p = __expf(sc[s] - tmax);
            sc[s] = p;
            l += p;
        }
        #pragma unroll 4
        for (int s = 0; s < 32; s++) {
            float p = sc[s];
            #pragma unroll
            for (int c = 0; c < 16; c++) {
                float4 v4 = Vs[s][c];
                acc[c].x += p * v4.x; acc[c].y += p * v4.y;
                acc[c].z += p * v4.z; acc[c].w += p * v4.w;
            }
        }
        mval = tmax;
        __syncthreads();
    }

    float inv = 1.f / l;
    float4* yrow = (float4*)(Y + (size_t)row * DIM + h * HD);
    #pragma unroll
    for (int c = 0; c < 16; c++) {
        float4 a = acc[c];
        a.x *= inv; a.y *= inv; a.z *= inv; a.w *= inv;
        yrow[c] = a;
    }
}

// ---------------- launch ----------------
extern "C" void kernel_launch(void* const* d_in, const int* in_sizes, int n_in,
                              void* d_out, int out_size)
{
    const float* x   = (const float*)d_in[0];
    const float* Wq  = (const float*)d_in[1];
    const float* Wk  = (const float*)d_in[2];
    const float* Wv  = (const float*)d_in[3];
    const float* Wo  = (const float*)d_in[4];
    const float* cosd= (const float*)d_in[5];
    const float* sind= (const float*)d_in[6];
    float* out = (float*)d_out;

    float *qp, *kp, *vp, *yp;
    cudaGetSymbolAddress((void**)&qp, g_q);
    cudaGetSymbolAddress((void**)&kp, g_k);
    cudaGetSymbolAddress((void**)&vp, g_v);
    cudaGetSymbolAddress((void**)&yp, g_y);

    constexpr int SMEM_128 = (4 * 128 * 36) * 4;  // 73728 B
    constexpr int SMEM_64  = (4 * 64  * 36) * 4;  // 36864 B
    cudaFuncSetAttribute(gemm_tf32<128,128>,
                         cudaFuncAttributeMaxDynamicSharedMemorySize, SMEM_128);
    cudaFuncSetAttribute(gemm_tf32<64,64>,
                         cudaFuncAttributeMaxDynamicSharedMemorySize, SMEM_64);

    // Q projection: [2048,2048]
    gemm_tf32<128,128><<<dim3(DIM/128, NSEQ/128), 256, SMEM_128>>>(x, Wq, qp, NSEQ, DIM, DIM);
    // K,V projections: [2048,256]
    gemm_tf32<64,64><<<dim3(KVDIM/64, NSEQ/64), 64, SMEM_64>>>(x, Wk, kp, NSEQ, KVDIM, DIM);
    gemm_tf32<64,64><<<dim3(KVDIM/64, NSEQ/64), 64, SMEM_64>>>(x, Wv, vp, NSEQ, KVDIM, DIM);

    // RoPE
    {
        int totq = NSEQ * HEADS * 32;
        rope_kernel<<<(totq + 255) / 256, 256>>>(qp, cosd, sind, HEADS, DIM);
        int totk = NSEQ * KVHEADS * 32;
        rope_kernel<<<(totk + 255) / 256, 256>>>(kp, cosd, sind, KVHEADS, KVDIM);
    }

    // attention
    attn_kernel<<<dim3(NSEQ/128, HEADS), 128>>>(qp, kp, vp, yp);

    // output projection
    gemm_tf32<128,128><<<dim3(DIM/128, NSEQ/128), 256, SMEM_128>>>(yp, Wo, out, NSEQ, DIM, DIM);
}

// round 3
// speedup vs baseline: 1.5117x; 1.4268x over previous
#include <cuda_runtime.h>
#include <cuda_bf16.h>
#include <math.h>
#include <stdint.h>

// Problem constants
#define NSEQ 2048
#define DIM  2048
#define HEADS 32
#define KVHEADS 4
#define HD 64
#define KVDIM (KVHEADS*HD)   // 256
#define REP (HEADS/KVHEADS)  // 8

// ---------------- scratch ----------------
__device__ float g_q[NSEQ * DIM];
__device__ float g_k[NSEQ * KVDIM];
__device__ float g_v[NSEQ * KVDIM];
__device__ float g_y[NSEQ * DIM];

// ---------------- tf32 helpers ----------------
__device__ __forceinline__ uint32_t f2tf(float x) {
    uint32_t r;
    asm("cvt.rna.tf32.f32 %0, %1;" : "=r"(r) : "f"(x));
    return r;
}

__device__ __forceinline__ void mma_tf32(float* d, const uint32_t* a, const uint32_t* b) {
    asm volatile(
        "mma.sync.aligned.m16n8k8.row.col.f32.tf32.tf32.f32 "
        "{%0,%1,%2,%3}, {%4,%5,%6,%7}, {%8,%9}, {%0,%1,%2,%3};"
        : "+f"(d[0]), "+f"(d[1]), "+f"(d[2]), "+f"(d[3])
        : "r"(a[0]), "r"(a[1]), "r"(a[2]), "r"(a[3]), "r"(b[0]), "r"(b[1]));
}

// ---------------- 3xTF32 NT GEMM (unchanged from R2) ----------------
template<int BM, int BN>
__global__ void __launch_bounds__(32*(BM/64)*(BN/32))
gemm_tf32(const float* __restrict__ A, const float* __restrict__ B,
          float* __restrict__ C, int M, int N, int K)
{
    constexpr int BK = 32;
    constexpr int LDSW = BK + 4;
    constexpr int WN_TILES = BN / 32;
    constexpr int WM_TILES = BM / 64;
    constexpr int WARPS = WM_TILES * WN_TILES;
    constexpr int THREADS = 32 * WARPS;
    constexpr int SA = BM * LDSW;
    constexpr int SB = BN * LDSW;

    extern __shared__ uint32_t sm[];
    uint32_t* Ah = sm;
    uint32_t* Al = sm + SA;
    uint32_t* Bh = sm + 2 * SA;
    uint32_t* Bl = sm + 2 * SA + SB;

    const int tid  = threadIdx.x;
    const int lane = tid & 31;
    const int warp = tid >> 5;
    const int wm   = warp / WN_TILES;
    const int wn   = warp % WN_TILES;
    const int m0   = blockIdx.y * BM;
    const int n0   = blockIdx.x * BN;

    float acc[4][4][4];
    #pragma unroll
    for (int i = 0; i < 4; i++)
        #pragma unroll
        for (int j = 0; j < 4; j++)
            #pragma unroll
            for (int r = 0; r < 4; r++) acc[i][j][r] = 0.f;

    for (int k0 = 0; k0 < K; k0 += BK) {
        #pragma unroll
        for (int i = tid; i < BM * (BK / 4); i += THREADS) {
            int row = i / (BK / 4);
            int kq  = (i % (BK / 4)) * 4;
            float4 v = *(const float4*)&A[(size_t)(m0 + row) * K + k0 + kq];
            float xs[4] = {v.x, v.y, v.z, v.w};
            #pragma unroll
            for (int e = 0; e < 4; e++) {
                uint32_t hi = f2tf(xs[e]);
                uint32_t lo = f2tf(xs[e] - __uint_as_float(hi));
                Ah[row * LDSW + kq + e] = hi;
                Al[row * LDSW + kq + e] = lo;
            }
        }
        #pragma unroll
        for (int i = tid; i < BN * (BK / 4); i += THREADS) {
            int row = i / (BK / 4);
            int kq  = (i % (BK / 4)) * 4;
            float4 v = *(const float4*)&B[(size_t)(n0 + row) * K + k0 + kq];
            float xs[4] = {v.x, v.y, v.z, v.w};
            #pragma unroll
            for (int e = 0; e < 4; e++) {
                uint32_t hi = f2tf(xs[e]);
                uint32_t lo = f2tf(xs[e] - __uint_as_float(hi));
                Bh[row * LDSW + kq + e] = hi;
                Bl[row * LDSW + kq + e] = lo;
            }
        }
        __syncthreads();

        #pragma unroll
        for (int ks = 0; ks < BK / 8; ks++) {
            uint32_t ah[4][4], al[4][4], bh[4][2], bl[4][2];
            const int c0 = ks * 8 + (lane & 3);
            #pragma unroll
            for (int i = 0; i < 4; i++) {
                int r0 = wm * 64 + i * 16 + (lane >> 2);
                ah[i][0] = Ah[r0 * LDSW + c0];
                ah[i][1] = Ah[(r0 + 8) * LDSW + c0];
                ah[i][2] = Ah[r0 * LDSW + c0 + 4];
                ah[i][3] = Ah[(r0 + 8) * LDSW + c0 + 4];
                al[i][0] = Al[r0 * LDSW + c0];
                al[i][1] = Al[(r0 + 8) * LDSW + c0];
                al[i][2] = Al[r0 * LDSW + c0 + 4];
                al[i][3] = Al[(r0 + 8) * LDSW + c0 + 4];
            }
            #pragma unroll
            for (int j = 0; j < 4; j++) {
                int nr = wn * 32 + j * 8 + (lane >> 2);
                bh[j][0] = Bh[nr * LDSW + c0];
                bh[j][1] = Bh[nr * LDSW + c0 + 4];
                bl[j][0] = Bl[nr * LDSW + c0];
                bl[j][1] = Bl[nr * LDSW + c0 + 4];
            }
            #pragma unroll
            for (int i = 0; i < 4; i++)
                #pragma unroll
                for (int j = 0; j < 4; j++) {
                    mma_tf32(acc[i][j], ah[i], bh[j]);
                    mma_tf32(acc[i][j], ah[i], bl[j]);
                    mma_tf32(acc[i][j], al[i], bh[j]);
                }
        }
        __syncthreads();
    }

    #pragma unroll
    for (int i = 0; i < 4; i++) {
        #pragma unroll
        for (int j = 0; j < 4; j++) {
            int row = m0 + wm * 64 + i * 16 + (lane >> 2);
            int col = n0 + wn * 32 + j * 8 + (lane & 3) * 2;
            float2 v01 = make_float2(acc[i][j][0], acc[i][j][1]);
            float2 v23 = make_float2(acc[i][j][2], acc[i][j][3]);
            *(float2*)&C[(size_t)row * N + col]       = v01;
            *(float2*)&C[(size_t)(row + 8) * N + col] = v23;
        }
    }
}

// ---------------- MMA flash attention (RoPE fused, causal) ----------------
// CTA: 128 q-rows x 1 head, 256 threads (8 warps x 16 rows). 64-key tiles.
// Scores: single tf32 (scale folded into Q). PV: 3xtf32 split.
#define LDP 68   // padded smem stride (words)

__global__ void __launch_bounds__(256)
attn_mma(const float* __restrict__ Qg, const float* __restrict__ Kg,
         const float* __restrict__ Vg, const float* __restrict__ cosd,
         const float* __restrict__ sind, float* __restrict__ Yg)
{
    extern __shared__ uint32_t sm[];
    uint32_t* Qs  = sm;                  // [128][LDP] tf32 (rope+scale applied)
    uint32_t* Ks  = Qs  + 128 * LDP;     // [64][LDP]  tf32 (rope applied)
    uint32_t* Vhi = Ks  + 64 * LDP;      // [64 d][LDP keys]
    uint32_t* Vlo = Vhi + 64 * LDP;
    float*    Pb  = (float*)(Vlo + 64 * LDP);  // [8 warps][16][LDP]

    const int tid  = threadIdx.x;
    const int lane = tid & 31;
    const int warp = tid >> 5;
    const int qb   = (gridDim.x - 1) - blockIdx.x;  // heavy blocks first
    const int h    = blockIdx.y;
    const int kvh  = h >> 3;
    float* Pw = Pb + warp * 16 * LDP;
    const int wrow = warp * 16;
    const int r0   = wrow + (lane >> 2);   // local q row (c-frag rows r0, r0+8)
    const int qz   = lane & 3;

    // ---- stage Q: rope + 0.125 scale, tf32 ----
    for (int i = tid; i < 128 * 32; i += 256) {
        int row = i >> 5, j = i & 31;
        int n = qb * 128 + row;
        const float* qr = Qg + (size_t)n * DIM + h * HD;
        float x0 = qr[j], x1 = qr[j + 32];
        float c0 = cosd[n * HD + j],      s0 = sind[n * HD + j];
        float c1 = cosd[n * HD + 32 + j], s1 = sind[n * HD + 32 + j];
        Qs[row * LDP + j]      = f2tf((x0 * c0 - x1 * s0) * 0.125f);
        Qs[row * LDP + 32 + j] = f2tf((x1 * c1 + x0 * s1) * 0.125f);
    }

    float yacc[8][4];
    #pragma unroll
    for (int nf = 0; nf < 8; nf++)
        #pragma unroll
        for (int r = 0; r < 4; r++) yacc[nf][r] = 0.f;
    float m0 = -1e30f, m1 = -1e30f, l0 = 0.f, l1 = 0.f;

    const int arow0 = qb * 128 + r0;
    const int arow1 = arow0 + 8;
    const int ntiles = 2 * qb + 2;

    for (int t = 0; t < ntiles; t++) {
        const int s0k = t * 64;
        // ---- stage K (rope) ----
        for (int i = tid; i < 64 * 32; i += 256) {
            int row = i >> 5, j = i & 31;
            int n = s0k + row;
            const float* kr = Kg + (size_t)n * KVDIM + kvh * HD;
            float x0 = kr[j], x1 = kr[j + 32];
            float c0 = cosd[n * HD + j],      s0 = sind[n * HD + j];
            float c1 = cosd[n * HD + 32 + j], s1 = sind[n * HD + 32 + j];
            Ks[row * LDP + j]      = f2tf(x0 * c0 - x1 * s0);
            Ks[row * LDP + 32 + j] = f2tf(x1 * c1 + x0 * s1);
        }
        // ---- stage V transposed, hi/lo split ----
        for (int i = tid; i < 64 * 64; i += 256) {
            int k = i >> 6, d = i & 63;
            float v = Vg[(size_t)(s0k + k) * KVDIM + kvh * HD + d];
            uint32_t hi = f2tf(v);
            uint32_t lo = f2tf(v - __uint_as_float(hi));
            Vhi[d * LDP + k] = hi;
            Vlo[d * LDP + k] = lo;
        }
        __syncthreads();

        // ---- scores: S[16 x 64] per warp ----
        float s[8][4];
        #pragma unroll
        for (int nf = 0; nf < 8; nf++)
            #pragma unroll
            for (int r = 0; r < 4; r++) s[nf][r] = 0.f;

        #pragma unroll
        for (int ki = 0; ki < 8; ki++) {
            const int c = ki * 8 + qz;
            uint32_t a[4];
            a[0] = Qs[r0 * LDP + c];
            a[1] = Qs[(r0 + 8) * LDP + c];
            a[2] = Qs[r0 * LDP + c + 4];
            a[3] = Qs[(r0 + 8) * LDP + c + 4];
            #pragma unroll
            for (int nf = 0; nf < 8; nf++) {
                const int krow = nf * 8 + (lane >> 2);
                uint32_t b[2];
                b[0] = Ks[krow * LDP + c];
                b[1] = Ks[krow * LDP + c + 4];
                mma_tf32(s[nf], a, b);
            }
        }

        // ---- causal mask (only diagonal-crossing tiles for this warp) ----
        if (s0k + 63 > qb * 128 + wrow) {
            #pragma unroll
            for (int nf = 0; nf < 8; nf++) {
                int key = s0k + nf * 8 + 2 * qz;
                if (key     > arow0) s[nf][0] = -1e30f;
                if (key + 1 > arow0) s[nf][1] = -1e30f;
                if (key     > arow1) s[nf][2] = -1e30f;
                if (key + 1 > arow1) s[nf][3] = -1e30f;
            }
        }

        // ---- online softmax ----
        float t0 = -1e30f, t1 = -1e30f;
        #pragma unroll
        for (int nf = 0; nf < 8; nf++) {
            t0 = fmaxf(t0, fmaxf(s[nf][0], s[nf][1]));
            t1 = fmaxf(t1, fmaxf(s[nf][2], s[nf][3]));
        }
        t0 = fmaxf(t0, __shfl_xor_sync(0xffffffff, t0, 1));
        t0 = fmaxf(t0, __shfl_xor_sync(0xffffffff, t0, 2));
        t1 = fmaxf(t1, __shfl_xor_sync(0xffffffff, t1, 1));
        t1 = fmaxf(t1, __shfl_xor_sync(0xffffffff, t1, 2));
        float nm0 = fmaxf(m0, t0), nm1 = fmaxf(m1, t1);
        float cor0 = __expf(m0 - nm0), cor1 = __expf(m1 - nm1);
        m0 = nm0; m1 = nm1;

        float ls0 = 0.f, ls1 = 0.f;
        #pragma unroll
        for (int nf = 0; nf < 8; nf++) {
            float p0 = __expf(s[nf][0] - m0);
            float p1 = __expf(s[nf][1] - m0);
            float p2 = __expf(s[nf][2] - m1);
            float p3 = __expf(s[nf][3] - m1);
            ls0 += p0 + p1;
            ls1 += p2 + p3;
            *(float2*)&Pw[(lane >> 2) * LDP + nf * 8 + 2 * qz]       = make_float2(p0, p1);
            *(float2*)&Pw[((lane >> 2) + 8) * LDP + nf * 8 + 2 * qz] = make_float2(p2, p3);
        }
        ls0 += __shfl_xor_sync(0xffffffff, ls0, 1);
        ls0 += __shfl_xor_sync(0xffffffff, ls0, 2);
        ls1 += __shfl_xor_sync(0xffffffff, ls1, 1);
        ls1 += __shfl_xor_sync(0xffffffff, ls1, 2);
        l0 = l0 * cor0 + ls0;
        l1 = l1 * cor1 + ls1;
        #pragma unroll
        for (int nf = 0; nf < 8; nf++) {
            yacc[nf][0] *= cor0; yacc[nf][1] *= cor0;
            yacc[nf][2] *= cor1; yacc[nf][3] *= cor1;
        }
        __syncwarp();

        // ---- PV: Y[16 x 64] += P[16 x 64keys] @ V[64keys x 64d], 3xtf32 ----
        #pragma unroll
        for (int ki = 0; ki < 8; ki++) {
            const int c = ki * 8 + qz;
            float p0 = Pw[(lane >> 2) * LDP + c];
            float p1 = Pw[((lane >> 2) + 8) * LDP + c];
            float p2 = Pw[(lane >> 2) * LDP + c + 4];
            float p3 = Pw[((lane >> 2) + 8) * LDP + c + 4];
            uint32_t ah[4], al[4];
            ah[0] = f2tf(p0); al[0] = f2tf(p0 - __uint_as_float(ah[0]));
            ah[1] = f2tf(p1); al[1] = f2tf(p1 - __uint_as_float(ah[1]));
            ah[2] = f2tf(p2); al[2] = f2tf(p2 - __uint_as_float(ah[2]));
            ah[3] = f2tf(p3); al[3] = f2tf(p3 - __uint_as_float(ah[3]));
            #pragma unroll
            for (int nf = 0; nf < 8; nf++) {
                const int vrow = nf * 8 + (lane >> 2);
                uint32_t bh[2], bl[2];
                bh[0] = Vhi[vrow * LDP + c];
                bh[1] = Vhi[vrow * LDP + c + 4];
                bl[0] = Vlo[vrow * LDP + c];
                bl[1] = Vlo[vrow * LDP + c + 4];
                mma_tf32(yacc[nf], ah, bh);
                mma_tf32(yacc[nf], al, bh);
                mma_tf32(yacc[nf], ah, bl);
            }
        }
        __syncthreads();
    }

    // ---- epilogue: normalize, store ----
    float i0 = 1.f / l0, i1 = 1.f / l1;
    #pragma unroll
    for (int nf = 0; nf < 8; nf++) {
        int col = h * HD + nf * 8 + 2 * qz;
        *(float2*)&Yg[(size_t)arow0 * DIM + col] =
            make_float2(yacc[nf][0] * i0, yacc[nf][1] * i0);
        *(float2*)&Yg[(size_t)arow1 * DIM + col] =
            make_float2(yacc[nf][2] * i1, yacc[nf][3] * i1);
    }
}

// ---------------- launch ----------------
extern "C" void kernel_launch(void* const* d_in, const int* in_sizes, int n_in,
                              void* d_out, int out_size)
{
    const float* x   = (const float*)d_in[0];
    const float* Wq  = (const float*)d_in[1];
    const float* Wk  = (const float*)d_in[2];
    const float* Wv  = (const float*)d_in[3];
    const float* Wo  = (const float*)d_in[4];
    const float* cosd= (const float*)d_in[5];
    const float* sind= (const float*)d_in[6];
    float* out = (float*)d_out;

    float *qp, *kp, *vp, *yp;
    cudaGetSymbolAddress((void**)&qp, g_q);
    cudaGetSymbolAddress((void**)&kp, g_k);
    cudaGetSymbolAddress((void**)&vp, g_v);
    cudaGetSymbolAddress((void**)&yp, g_y);

    constexpr int SMEM_128 = (4 * 128 * 36) * 4;  // 73728 B
    constexpr int SMEM_64  = (4 * 64  * 36) * 4;  // 36864 B
    constexpr int SMEM_ATTN = (128*LDP + 64*LDP + 2*64*LDP + 8*16*LDP) * 4; // 121856 B
    cudaFuncSetAttribute(gemm_tf32<128,128>,
                         cudaFuncAttributeMaxDynamicSharedMemorySize, SMEM_128);
    cudaFuncSetAttribute(gemm_tf32<64,64>,
                         cudaFuncAttributeMaxDynamicSharedMemorySize, SMEM_64);
    cudaFuncSetAttribute(attn_mma,
                         cudaFuncAttributeMaxDynamicSharedMemorySize, SMEM_ATTN);

    // 1: Q projection
    gemm_tf32<128,128><<<dim3(DIM/128, NSEQ/128), 256, SMEM_128>>>(x, Wq, qp, NSEQ, DIM, DIM);
    // 2,3: K,V projections
    gemm_tf32<64,64><<<dim3(KVDIM/64, NSEQ/64), 64, SMEM_64>>>(x, Wk, kp, NSEQ, KVDIM, DIM);
    gemm_tf32<64,64><<<dim3(KVDIM/64, NSEQ/64), 64, SMEM_64>>>(x, Wv, vp, NSEQ, KVDIM, DIM);
    // 4: fused rope + flash attention (profiled slot)
    attn_mma<<<dim3(16, HEADS), 256, SMEM_ATTN>>>(qp, kp, vp, cosd, sind, yp);
    // 5: output projection
    gemm_tf32<128,128><<<dim3(DIM/128, NSEQ/128), 256, SMEM_128>>>(yp, Wo, out, NSEQ, DIM, DIM);
}

// round 4
// speedup vs baseline: 1.9172x; 1.2683x over previous
#include <cuda_runtime.h>
#include <cuda_bf16.h>
#include <math.h>
#include <stdint.h>

// Problem constants
#define NSEQ 2048
#define DIM  2048
#define HEADS 32
#define KVHEADS 4
#define HD 64
#define KVDIM (KVHEADS*HD)   // 256
#define REP (HEADS/KVHEADS)  // 8

// ---------------- scratch ----------------
__device__ float g_q[NSEQ * DIM];
__device__ float g_k[NSEQ * KVDIM];
__device__ float g_v[NSEQ * KVDIM];
__device__ float g_y[NSEQ * DIM];

// ---------------- tf32 helpers ----------------
__device__ __forceinline__ uint32_t f2tf(float x) {
    uint32_t r;
    asm("cvt.rna.tf32.f32 %0, %1;" : "=r"(r) : "f"(x));
    return r;
}

__device__ __forceinline__ void mma_tf32(float* d, const uint32_t* a, const uint32_t* b) {
    asm volatile(
        "mma.sync.aligned.m16n8k8.row.col.f32.tf32.tf32.f32 "
        "{%0,%1,%2,%3}, {%4,%5,%6,%7}, {%8,%9}, {%0,%1,%2,%3};"
        : "+f"(d[0]), "+f"(d[1]), "+f"(d[2]), "+f"(d[3])
        : "r"(a[0]), "r"(a[1]), "r"(a[2]), "r"(a[3]), "r"(b[0]), "r"(b[1]));
}

// ---------------- 3xTF32 NT GEMM, register-prefetch pipelined ----------------
// C[m][n] = sum_k A[m][k]*B[n][k]. Warp tile 64x32 (4x4 frags of m16n8k8).
template<int BM, int BN>
__global__ void __launch_bounds__(32*(BM/64)*(BN/32))
gemm_tf32(const float* __restrict__ A, const float* __restrict__ B,
          float* __restrict__ C, int M, int N, int K, int moff)
{
    constexpr int BK = 32;
    constexpr int LDSW = BK + 4;
    constexpr int WN_TILES = BN / 32;
    constexpr int WM_TILES = BM / 64;
    constexpr int WARPS = WM_TILES * WN_TILES;
    constexpr int THREADS = 32 * WARPS;
    constexpr int SA = BM * LDSW;
    constexpr int SB = BN * LDSW;
    constexpr int A4T = BM * (BK/4) / THREADS;   // float4 loads per thread (A)
    constexpr int B4T = BN * (BK/4) / THREADS;

    extern __shared__ uint32_t sm[];
    uint32_t* Ah = sm;
    uint32_t* Al = sm + SA;
    uint32_t* Bh = sm + 2 * SA;
    uint32_t* Bl = sm + 2 * SA + SB;

    const int tid  = threadIdx.x;
    const int lane = tid & 31;
    const int warp = tid >> 5;
    const int wm   = warp / WN_TILES;
    const int wn   = warp % WN_TILES;
    const int m0   = blockIdx.y * BM + moff;
    const int n0   = blockIdx.x * BN;

    float acc[4][4][4];
    #pragma unroll
    for (int i = 0; i < 4; i++)
        #pragma unroll
        for (int j = 0; j < 4; j++)
            #pragma unroll
            for (int r = 0; r < 4; r++) acc[i][j][r] = 0.f;

    float4 pa[A4T], pb[B4T];
    // prologue fetch (k0 = 0)
    #pragma unroll
    for (int i = 0; i < A4T; i++) {
        int idx = tid + i * THREADS;
        int row = idx / (BK/4), kq = (idx % (BK/4)) * 4;
        pa[i] = *(const float4*)&A[(size_t)(m0 + row) * K + kq];
    }
    #pragma unroll
    for (int i = 0; i < B4T; i++) {
        int idx = tid + i * THREADS;
        int row = idx / (BK/4), kq = (idx % (BK/4)) * 4;
        pb[i] = *(const float4*)&B[(size_t)(n0 + row) * K + kq];
    }

    for (int k0 = 0; k0 < K; k0 += BK) {
        // ---- split + store prefetched tile ----
        #pragma unroll
        for (int i = 0; i < A4T; i++) {
            int idx = tid + i * THREADS;
            int row = idx / (BK/4), kq = (idx % (BK/4)) * 4;
            float xs[4] = {pa[i].x, pa[i].y, pa[i].z, pa[i].w};
            #pragma unroll
            for (int e = 0; e < 4; e++) {
                uint32_t hi = f2tf(xs[e]);
                Ah[row * LDSW + kq + e] = hi;
                Al[row * LDSW + kq + e] = f2tf(xs[e] - __uint_as_float(hi));
            }
        }
        #pragma unroll
        for (int i = 0; i < B4T; i++) {
            int idx = tid + i * THREADS;
            int row = idx / (BK/4), kq = (idx % (BK/4)) * 4;
            float xs[4] = {pb[i].x, pb[i].y, pb[i].z, pb[i].w};
            #pragma unroll
            for (int e = 0; e < 4; e++) {
                uint32_t hi = f2tf(xs[e]);
                Bh[row * LDSW + kq + e] = hi;
                Bl[row * LDSW + kq + e] = f2tf(xs[e] - __uint_as_float(hi));
            }
        }
        __syncthreads();

        // ---- prefetch next tile (overlaps with MMA below) ----
        if (k0 + BK < K) {
            #pragma unroll
            for (int i = 0; i < A4T; i++) {
                int idx = tid + i * THREADS;
                int row = idx / (BK/4), kq = (idx % (BK/4)) * 4;
                pa[i] = *(const float4*)&A[(size_t)(m0 + row) * K + k0 + BK + kq];
            }
            #pragma unroll
            for (int i = 0; i < B4T; i++) {
                int idx = tid + i * THREADS;
                int row = idx / (BK/4), kq = (idx % (BK/4)) * 4;
                pb[i] = *(const float4*)&B[(size_t)(n0 + row) * K + k0 + BK + kq];
            }
        }

        #pragma unroll
        for (int ks = 0; ks < BK / 8; ks++) {
            uint32_t ah[4][4], al[4][4], bh[4][2], bl[4][2];
            const int c0 = ks * 8 + (lane & 3);
            #pragma unroll
            for (int i = 0; i < 4; i++) {
                int r0 = wm * 64 + i * 16 + (lane >> 2);
                ah[i][0] = Ah[r0 * LDSW + c0];
                ah[i][1] = Ah[(r0 + 8) * LDSW + c0];
                ah[i][2] = Ah[r0 * LDSW + c0 + 4];
                ah[i][3] = Ah[(r0 + 8) * LDSW + c0 + 4];
                al[i][0] = Al[r0 * LDSW + c0];
                al[i][1] = Al[(r0 + 8) * LDSW + c0];
                al[i][2] = Al[r0 * LDSW + c0 + 4];
                al[i][3] = Al[(r0 + 8) * LDSW + c0 + 4];
            }
            #pragma unroll
            for (int j = 0; j < 4; j++) {
                int nr = wn * 32 + j * 8 + (lane >> 2);
                bh[j][0] = Bh[nr * LDSW + c0];
                bh[j][1] = Bh[nr * LDSW + c0 + 4];
                bl[j][0] = Bl[nr * LDSW + c0];
                bl[j][1] = Bl[nr * LDSW + c0 + 4];
            }
            #pragma unroll
            for (int i = 0; i < 4; i++)
                #pragma unroll
                for (int j = 0; j < 4; j++) {
                    mma_tf32(acc[i][j], ah[i], bh[j]);
                    mma_tf32(acc[i][j], ah[i], bl[j]);
                    mma_tf32(acc[i][j], al[i], bh[j]);
                }
        }
        __syncthreads();
    }

    #pragma unroll
    for (int i = 0; i < 4; i++) {
        #pragma unroll
        for (int j = 0; j < 4; j++) {
            int row = m0 + wm * 64 + i * 16 + (lane >> 2);
            int col = n0 + wn * 32 + j * 8 + (lane & 3) * 2;
            *(float2*)&C[(size_t)row * N + col]       = make_float2(acc[i][j][0], acc[i][j][1]);
            *(float2*)&C[(size_t)(row + 8) * N + col] = make_float2(acc[i][j][2], acc[i][j][3]);
        }
    }
}

// ---------------- MMA flash attention (RoPE fused, causal) ----------------
// CTA: 128 q-rows x 1 head, 256 threads (8 warps x 16 rows). 64-key tiles.
// Scores: single tf32 (scale folded into Q). PV: 3xtf32, P transposed via shfl.
#define LDP 68

__global__ void __launch_bounds__(256, 2)
attn_mma(const float* __restrict__ Qg, const float* __restrict__ Kg,
         const float* __restrict__ Vg, const float* __restrict__ cosd,
         const float* __restrict__ sind, float* __restrict__ Yg)
{
    extern __shared__ uint32_t sm[];
    uint32_t* Qs  = sm;                  // [128][LDP]
    uint32_t* Ks  = Qs  + 128 * LDP;     // [64][LDP]
    uint32_t* Vhi = Ks  + 64 * LDP;      // [64 d][LDP keys]
    uint32_t* Vlo = Vhi + 64 * LDP;

    const int tid  = threadIdx.x;
    const int lane = tid & 31;
    const int warp = tid >> 5;
    const int qb   = (gridDim.x - 1) - blockIdx.x;  // heavy blocks first
    const int h    = blockIdx.y;
    const int kvh  = h >> 3;
    const int wrow = warp * 16;
    const int r0   = wrow + (lane >> 2);
    const int qz   = lane & 3;

    // ---- stage Q: rope + 0.125 scale, tf32 ----
    for (int i = tid; i < 128 * 32; i += 256) {
        int row = i >> 5, j = i & 31;
        int n = qb * 128 + row;
        const float* qr = Qg + (size_t)n * DIM + h * HD;
        float x0 = qr[j], x1 = qr[j + 32];
        float c0 = cosd[n * HD + j],      s0 = sind[n * HD + j];
        float c1 = cosd[n * HD + 32 + j], s1 = sind[n * HD + 32 + j];
        Qs[row * LDP + j]      = f2tf((x0 * c0 - x1 * s0) * 0.125f);
        Qs[row * LDP + 32 + j] = f2tf((x1 * c1 + x0 * s1) * 0.125f);
    }

    float yacc[8][4];
    #pragma unroll
    for (int nf = 0; nf < 8; nf++)
        #pragma unroll
        for (int r = 0; r < 4; r++) yacc[nf][r] = 0.f;
    float m0 = -1e30f, m1 = -1e30f, l0 = 0.f, l1 = 0.f;

    const int arow0 = qb * 128 + r0;
    const int arow1 = arow0 + 8;
    const int ntiles = 2 * qb + 2;

    for (int t = 0; t < ntiles; t++) {
        const int s0k = t * 64;
        // ---- stage K (rope) ----
        for (int i = tid; i < 64 * 32; i += 256) {
            int row = i >> 5, j = i & 31;
            int n = s0k + row;
            const float* kr = Kg + (size_t)n * KVDIM + kvh * HD;
            float x0 = kr[j], x1 = kr[j + 32];
            float c0 = cosd[n * HD + j],      s0 = sind[n * HD + j];
            float c1 = cosd[n * HD + 32 + j], s1 = sind[n * HD + 32 + j];
            Ks[row * LDP + j]      = f2tf(x0 * c0 - x1 * s0);
            Ks[row * LDP + 32 + j] = f2tf(x1 * c1 + x0 * s1);
        }
        // ---- stage V transposed, hi/lo split ----
        for (int i = tid; i < 64 * 64; i += 256) {
            int k = i >> 6, d = i & 63;
            float v = Vg[(size_t)(s0k + k) * KVDIM + kvh * HD + d];
            uint32_t hi = f2tf(v);
            Vhi[d * LDP + k] = hi;
            Vlo[d * LDP + k] = f2tf(v - __uint_as_float(hi));
        }
        __syncthreads();

        // ---- scores: S[16 x 64] per warp ----
        float s[8][4];
        #pragma unroll
        for (int nf = 0; nf < 8; nf++)
            #pragma unroll
            for (int r = 0; r < 4; r++) s[nf][r] = 0.f;

        #pragma unroll
        for (int ki = 0; ki < 8; ki++) {
            const int c = ki * 8 + qz;
            uint32_t a[4];
            a[0] = Qs[r0 * LDP + c];
            a[1] = Qs[(r0 + 8) * LDP + c];
            a[2] = Qs[r0 * LDP + c + 4];
            a[3] = Qs[(r0 + 8) * LDP + c + 4];
            #pragma unroll
            for (int nf = 0; nf < 8; nf++) {
                const int krow = nf * 8 + (lane >> 2);
                uint32_t b[2];
                b[0] = Ks[krow * LDP + c];
                b[1] = Ks[krow * LDP + c + 4];
                mma_tf32(s[nf], a, b);
            }
        }

        // ---- causal mask ----
        if (s0k + 63 > qb * 128 + wrow) {
            #pragma unroll
            for (int nf = 0; nf < 8; nf++) {
                int key = s0k + nf * 8 + 2 * qz;
                if (key     > arow0) s[nf][0] = -1e30f;
                if (key + 1 > arow0) s[nf][1] = -1e30f;
                if (key     > arow1) s[nf][2] = -1e30f;
                if (key + 1 > arow1) s[nf][3] = -1e30f;
            }
        }

        // ---- online softmax ----
        float t0 = -1e30f, t1 = -1e30f;
        #pragma unroll
        for (int nf = 0; nf < 8; nf++) {
            t0 = fmaxf(t0, fmaxf(s[nf][0], s[nf][1]));
            t1 = fmaxf(t1, fmaxf(s[nf][2], s[nf][3]));
        }
        t0 = fmaxf(t0, __shfl_xor_sync(0xffffffff, t0, 1));
        t0 = fmaxf(t0, __shfl_xor_sync(0xffffffff, t0, 2));
        t1 = fmaxf(t1, __shfl_xor_sync(0xffffffff, t1, 1));
        t1 = fmaxf(t1, __shfl_xor_sync(0xffffffff, t1, 2));
        float nm0 = fmaxf(m0, t0), nm1 = fmaxf(m1, t1);
        float cor0 = __expf(m0 - nm0), cor1 = __expf(m1 - nm1);
        m0 = nm0; m1 = nm1;

        float ls0 = 0.f, ls1 = 0.f;
        #pragma unroll
        for (int nf = 0; nf < 8; nf++) {
            s[nf][0] = __expf(s[nf][0] - m0);
            s[nf][1] = __expf(s[nf][1] - m0);
            s[nf][2] = __expf(s[nf][2] - m1);
            s[nf][3] = __expf(s[nf][3] - m1);
            ls0 += s[nf][0] + s[nf][1];
            ls1 += s[nf][2] + s[nf][3];
        }
        ls0 += __shfl_xor_sync(0xffffffff, ls0, 1);
        ls0 += __shfl_xor_sync(0xffffffff, ls0, 2);
        ls1 += __shfl_xor_sync(0xffffffff, ls1, 1);
        ls1 += __shfl_xor_sync(0xffffffff, ls1, 2);
        l0 = l0 * cor0 + ls0;
        l1 = l1 * cor1 + ls1;
        #pragma unroll
        for (int nf = 0; nf < 8; nf++) {
            yacc[nf][0] *= cor0; yacc[nf][1] *= cor0;
            yacc[nf][2] *= cor1; yacc[nf][3] *= cor1;
        }

        // ---- PV: transpose P c-frag -> a-frag via intra-quad shuffles ----
        #pragma unroll
        for (int ki = 0; ki < 8; ki++) {
            const int srcA = (lane & ~3) | (qz >> 1);
            const int srcB = srcA + 2;
            float x0 = __shfl_sync(0xffffffff, s[ki][0], srcA);
            float x1 = __shfl_sync(0xffffffff, s[ki][1], srcA);
            float x2 = __shfl_sync(0xffffffff, s[ki][2], srcA);
            float x3 = __shfl_sync(0xffffffff, s[ki][3], srcA);
            float y0 = __shfl_sync(0xffffffff, s[ki][0], srcB);
            float y1 = __shfl_sync(0xffffffff, s[ki][1], srcB);
            float y2 = __shfl_sync(0xffffffff, s[ki][2], srcB);
            float y3 = __shfl_sync(0xffffffff, s[ki][3], srcB);
            bool odd = (qz & 1);
            float pA0 = odd ? x1 : x0;   // (r0,      ki*8+qz)
            float pA1 = odd ? x3 : x2;   // (r0+8,    ki*8+qz)
            float pA2 = odd ? y1 : y0;   // (r0,      ki*8+qz+4)
            float pA3 = odd ? y3 : y2;   // (r0+8,    ki*8+qz+4)
            uint32_t ah[4], al[4];
            ah[0] = f2tf(pA0); al[0] = f2tf(pA0 - __uint_as_float(ah[0]));
            ah[1] = f2tf(pA1); al[1] = f2tf(pA1 - __uint_as_float(ah[1]));
            ah[2] = f2tf(pA2); al[2] = f2tf(pA2 - __uint_as_float(ah[2]));
            ah[3] = f2tf(pA3); al[3] = f2tf(pA3 - __uint_as_float(ah[3]));
            const int c = ki * 8 + qz;
            #pragma unroll
            for (int nf = 0; nf < 8; nf++) {
                const int vrow = nf * 8 + (lane >> 2);
                uint32_t bh[2], bl[2];
                bh[0] = Vhi[vrow * LDP + c];
                bh[1] = Vhi[vrow * LDP + c + 4];
                bl[0] = Vlo[vrow * LDP + c];
                bl[1] = Vlo[vrow * LDP + c + 4];
                mma_tf32(yacc[nf], ah, bh);
                mma_tf32(yacc[nf], al, bh);
                mma_tf32(yacc[nf], ah, bl);
            }
        }
        __syncthreads();
    }

    // ---- epilogue ----
    float i0 = 1.f / l0, i1 = 1.f / l1;
    #pragma unroll
    for (int nf = 0; nf < 8; nf++) {
        int col = h * HD + nf * 8 + 2 * qz;
        *(float2*)&Yg[(size_t)arow0 * DIM + col] =
            make_float2(yacc[nf][0] * i0, yacc[nf][1] * i0);
        *(float2*)&Yg[(size_t)arow1 * DIM + col] =
            make_float2(yacc[nf][2] * i1, yacc[nf][3] * i1);
    }
}

// ---------------- launch ----------------
extern "C" void kernel_launch(void* const* d_in, const int* in_sizes, int n_in,
                              void* d_out, int out_size)
{
    const float* x   = (const float*)d_in[0];
    const float* Wq  = (const float*)d_in[1];
    const float* Wk  = (const float*)d_in[2];
    const float* Wv  = (const float*)d_in[3];
    const float* Wo  = (const float*)d_in[4];
    const float* cosd= (const float*)d_in[5];
    const float* sind= (const float*)d_in[6];
    float* out = (float*)d_out;

    float *qp, *kp, *vp, *yp;
    cudaGetSymbolAddress((void**)&qp, g_q);
    cudaGetSymbolAddress((void**)&kp, g_k);
    cudaGetSymbolAddress((void**)&vp, g_v);
    cudaGetSymbolAddress((void**)&yp, g_y);

    constexpr int SMEM_128 = (4 * 128 * 36) * 4;               // 73728 B
    constexpr int SMEM_64  = (4 * 64  * 36) * 4;               // 36864 B
    constexpr int SMEM_ATTN = (128 + 64 + 128) * LDP * 4;      // 87040 B
    cudaFuncSetAttribute(gemm_tf32<128,128>,
                         cudaFuncAttributeMaxDynamicSharedMemorySize, SMEM_128);
    cudaFuncSetAttribute(gemm_tf32<64,64>,
                         cudaFuncAttributeMaxDynamicSharedMemorySize, SMEM_64);
    cudaFuncSetAttribute(attn_mma,
                         cudaFuncAttributeMaxDynamicSharedMemorySize, SMEM_ATTN);

    // 1,2: K,V projections
    gemm_tf32<64,64><<<dim3(KVDIM/64, NSEQ/64), 64, SMEM_64>>>(x, Wk, kp, NSEQ, KVDIM, DIM, 0);
    gemm_tf32<64,64><<<dim3(KVDIM/64, NSEQ/64), 64, SMEM_64>>>(x, Wv, vp, NSEQ, KVDIM, DIM, 0);
    // 3,4: Q projection split in half (slot 4 = profiled big GEMM)
    gemm_tf32<128,128><<<dim3(DIM/128, NSEQ/256), 256, SMEM_128>>>(x, Wq, qp, NSEQ, DIM, DIM, 0);
    gemm_tf32<128,128><<<dim3(DIM/128, NSEQ/256), 256, SMEM_128>>>(x, Wq, qp, NSEQ, DIM, DIM, NSEQ/2);
    // 5: fused rope + flash attention
    attn_mma<<<dim3(16, HEADS), 256, SMEM_ATTN>>>(qp, kp, vp, cosd, sind, yp);
    // 6: output projection
    gemm_tf32<128,128><<<dim3(DIM/128, NSEQ/128), 256, SMEM_128>>>(yp, Wo, out, NSEQ, DIM, DIM, 0);
}

// round 5
// speedup vs baseline: 2.8168x; 1.4692x over previous
#include <cuda_runtime.h>
#include <cuda_bf16.h>
#include <math.h>
#include <stdint.h>

// Problem constants
#define NSEQ 2048
#define DIM  2048
#define HEADS 32
#define KVHEADS 4
#define HD 64
#define KVDIM (KVHEADS*HD)   // 256
#define REP (HEADS/KVHEADS)  // 8

// ---------------- scratch ----------------
__device__ float g_q[NSEQ * DIM];
__device__ float g_k[NSEQ * KVDIM];
__device__ float g_v[NSEQ * KVDIM];
__device__ float g_y[NSEQ * DIM];

// ---------------- helpers ----------------
__device__ __forceinline__ uint32_t f2tf(float x) {
    uint32_t r;
    asm("cvt.rna.tf32.f32 %0, %1;" : "=r"(r) : "f"(x));
    return r;
}

__device__ __forceinline__ uint32_t pkbf(float x0, float x1) {
    __nv_bfloat162 h = __floats2bfloat162_rn(x0, x1);
    return *reinterpret_cast<uint32_t*>(&h);
}

// split x into hi(bf16) + lo(bf16) packed pairs
__device__ __forceinline__ void split2(float x0, float x1, uint32_t& hi, uint32_t& lo) {
    float h0 = __bfloat162float(__float2bfloat16(x0));
    float h1 = __bfloat162float(__float2bfloat16(x1));
    hi = pkbf(h0, h1);
    lo = pkbf(x0 - h0, x1 - h1);
}

__device__ __forceinline__ void mma_tf32(float* d, const uint32_t* a, const uint32_t* b) {
    asm volatile(
        "mma.sync.aligned.m16n8k8.row.col.f32.tf32.tf32.f32 "
        "{%0,%1,%2,%3}, {%4,%5,%6,%7}, {%8,%9}, {%0,%1,%2,%3};"
        : "+f"(d[0]), "+f"(d[1]), "+f"(d[2]), "+f"(d[3])
        : "r"(a[0]), "r"(a[1]), "r"(a[2]), "r"(a[3]), "r"(b[0]), "r"(b[1]));
}

__device__ __forceinline__ void mma_bf16(float* d, const uint32_t* a, const uint32_t* b) {
    asm volatile(
        "mma.sync.aligned.m16n8k16.row.col.f32.bf16.bf16.f32 "
        "{%0,%1,%2,%3}, {%4,%5,%6,%7}, {%8,%9}, {%0,%1,%2,%3};"
        : "+f"(d[0]), "+f"(d[1]), "+f"(d[2]), "+f"(d[3])
        : "r"(a[0]), "r"(a[1]), "r"(a[2]), "r"(a[3]), "r"(b[0]), "r"(b[1]));
}

// ---------------- 3xBF16 NT GEMM, register-prefetch pipelined ----------------
// C[m][n] = sum_k A[m][k]*B[n][k]. Warp tile 64x32 (4x4 frags of m16n8k16).
// smem holds packed bf16x2 (k-pairs), hi and lo planes.
template<int BM, int BN>
__global__ void __launch_bounds__(32*(BM/64)*(BN/32))
gemm_bf16(const float* __restrict__ A, const float* __restrict__ B,
          float* __restrict__ C, int M, int N, int K, int moff)
{
    constexpr int BK = 32;
    constexpr int LDSW = BK/2 + 4;      // 20 u32 per row: conflict-free frag reads
    constexpr int WN_TILES = BN / 32;
    constexpr int WM_TILES = BM / 64;
    constexpr int WARPS = WM_TILES * WN_TILES;
    constexpr int THREADS = 32 * WARPS;
    constexpr int SA = BM * LDSW;
    constexpr int SB = BN * LDSW;
    constexpr int A4T = BM * (BK/4) / THREADS;
    constexpr int B4T = BN * (BK/4) / THREADS;

    extern __shared__ uint32_t sm[];
    uint32_t* Ah = sm;
    uint32_t* Al = sm + SA;
    uint32_t* Bh = sm + 2 * SA;
    uint32_t* Bl = sm + 2 * SA + SB;

    const int tid  = threadIdx.x;
    const int lane = tid & 31;
    const int warp = tid >> 5;
    const int wm   = warp / WN_TILES;
    const int wn   = warp % WN_TILES;
    const int m0   = blockIdx.y * BM + moff;
    const int n0   = blockIdx.x * BN;
    const int qz   = lane & 3;

    float acc[4][4][4];
    #pragma unroll
    for (int i = 0; i < 4; i++)
        #pragma unroll
        for (int j = 0; j < 4; j++)
            #pragma unroll
            for (int r = 0; r < 4; r++) acc[i][j][r] = 0.f;

    float4 pa[A4T], pb[B4T];
    #pragma unroll
    for (int i = 0; i < A4T; i++) {
        int idx = tid + i * THREADS;
        int row = idx / (BK/4), kq = (idx % (BK/4)) * 4;
        pa[i] = *(const float4*)&A[(size_t)(m0 + row) * K + kq];
    }
    #pragma unroll
    for (int i = 0; i < B4T; i++) {
        int idx = tid + i * THREADS;
        int row = idx / (BK/4), kq = (idx % (BK/4)) * 4;
        pb[i] = *(const float4*)&B[(size_t)(n0 + row) * K + kq];
    }

    for (int k0 = 0; k0 < K; k0 += BK) {
        // ---- split + store prefetched tile (packed bf16x2) ----
        #pragma unroll
        for (int i = 0; i < A4T; i++) {
            int idx = tid + i * THREADS;
            int row = idx / (BK/4), kq = (idx % (BK/4)) * 4;
            uint32_t h01, l01, h23, l23;
            split2(pa[i].x, pa[i].y, h01, l01);
            split2(pa[i].z, pa[i].w, h23, l23);
            Ah[row * LDSW + kq/2]     = h01;
            Ah[row * LDSW + kq/2 + 1] = h23;
            Al[row * LDSW + kq/2]     = l01;
            Al[row * LDSW + kq/2 + 1] = l23;
        }
        #pragma unroll
        for (int i = 0; i < B4T; i++) {
            int idx = tid + i * THREADS;
            int row = idx / (BK/4), kq = (idx % (BK/4)) * 4;
            uint32_t h01, l01, h23, l23;
            split2(pb[i].x, pb[i].y, h01, l01);
            split2(pb[i].z, pb[i].w, h23, l23);
            Bh[row * LDSW + kq/2]     = h01;
            Bh[row * LDSW + kq/2 + 1] = h23;
            Bl[row * LDSW + kq/2]     = l01;
            Bl[row * LDSW + kq/2 + 1] = l23;
        }
        __syncthreads();

        // ---- prefetch next tile (overlaps MMA) ----
        if (k0 + BK < K) {
            #pragma unroll
            for (int i = 0; i < A4T; i++) {
                int idx = tid + i * THREADS;
                int row = idx / (BK/4), kq = (idx % (BK/4)) * 4;
                pa[i] = *(const float4*)&A[(size_t)(m0 + row) * K + k0 + BK + kq];
            }
            #pragma unroll
            for (int i = 0; i < B4T; i++) {
                int idx = tid + i * THREADS;
                int row = idx / (BK/4), kq = (idx % (BK/4)) * 4;
                pb[i] = *(const float4*)&B[(size_t)(n0 + row) * K + k0 + BK + kq];
            }
        }

        // ---- 2 k16-steps per BK=32 ----
        #pragma unroll
        for (int ks = 0; ks < 2; ks++) {
            const int c0 = ks * 8 + qz;
            uint32_t ah[4][4], al[4][4], bh[4][2], bl[4][2];
            #pragma unroll
            for (int i = 0; i < 4; i++) {
                int r0 = wm * 64 + i * 16 + (lane >> 2);
                ah[i][0] = Ah[r0 * LDSW + c0];
                ah[i][1] = Ah[(r0 + 8) * LDSW + c0];
                ah[i][2] = Ah[r0 * LDSW + c0 + 4];
                ah[i][3] = Ah[(r0 + 8) * LDSW + c0 + 4];
                al[i][0] = Al[r0 * LDSW + c0];
                al[i][1] = Al[(r0 + 8) * LDSW + c0];
                al[i][2] = Al[r0 * LDSW + c0 + 4];
                al[i][3] = Al[(r0 + 8) * LDSW + c0 + 4];
            }
            #pragma unroll
            for (int j = 0; j < 4; j++) {
                int nr = wn * 32 + j * 8 + (lane >> 2);
                bh[j][0] = Bh[nr * LDSW + c0];
                bh[j][1] = Bh[nr * LDSW + c0 + 4];
                bl[j][0] = Bl[nr * LDSW + c0];
                bl[j][1] = Bl[nr * LDSW + c0 + 4];
            }
            #pragma unroll
            for (int i = 0; i < 4; i++)
                #pragma unroll
                for (int j = 0; j < 4; j++) {
                    mma_bf16(acc[i][j], ah[i], bh[j]);
                    mma_bf16(acc[i][j], al[i], bh[j]);
                    mma_bf16(acc[i][j], ah[i], bl[j]);
                }
        }
        __syncthreads();
    }

    #pragma unroll
    for (int i = 0; i < 4; i++) {
        #pragma unroll
        for (int j = 0; j < 4; j++) {
            int row = m0 + wm * 64 + i * 16 + (lane >> 2);
            int col = n0 + wn * 32 + j * 8 + qz * 2;
            *(float2*)&C[(size_t)row * N + col]       = make_float2(acc[i][j][0], acc[i][j][1]);
            *(float2*)&C[(size_t)(row + 8) * N + col] = make_float2(acc[i][j][2], acc[i][j][3]);
        }
    }
}

// ---------------- MMA flash attention (RoPE fused, causal) ----------------
// CTA: 128 q-rows x 1 head, 256 threads (8 warps x 16 rows). 64-key tiles.
// Scores: single tf32 (scale folded into Q). PV: 3xbf16, P c-frag == a-frag (no transpose).
#define LDP 68
#define LDV 36

__global__ void __launch_bounds__(256, 2)
attn_mma(const float* __restrict__ Qg, const float* __restrict__ Kg,
         const float* __restrict__ Vg, const float* __restrict__ cosd,
         const float* __restrict__ sind, float* __restrict__ Yg)
{
    extern __shared__ uint32_t sm[];
    uint32_t* Qs  = sm;                  // [128][LDP] tf32
    uint32_t* Ks  = Qs  + 128 * LDP;     // [64][LDP]  tf32
    uint32_t* Vhi = Ks  + 64 * LDP;      // [64 d][LDV kp]  packed bf16x2 (key pairs)
    uint32_t* Vlo = Vhi + 64 * LDV;

    const int tid  = threadIdx.x;
    const int lane = tid & 31;
    const int warp = tid >> 5;
    const int qb   = (gridDim.x - 1) - blockIdx.x;  // heavy blocks first
    const int h    = blockIdx.y;
    const int kvh  = h >> 3;
    const int wrow = warp * 16;
    const int r0   = wrow + (lane >> 2);
    const int qz   = lane & 3;

    // ---- stage Q: rope + 0.125 scale, tf32 ----
    for (int i = tid; i < 128 * 32; i += 256) {
        int row = i >> 5, j = i & 31;
        int n = qb * 128 + row;
        const float* qr = Qg + (size_t)n * DIM + h * HD;
        float x0 = qr[j], x1 = qr[j + 32];
        float c0 = cosd[n * HD + j],      s0 = sind[n * HD + j];
        float c1 = cosd[n * HD + 32 + j], s1 = sind[n * HD + 32 + j];
        Qs[row * LDP + j]      = f2tf((x0 * c0 - x1 * s0) * 0.125f);
        Qs[row * LDP + 32 + j] = f2tf((x1 * c1 + x0 * s1) * 0.125f);
    }

    float yacc[8][4];
    #pragma unroll
    for (int nf = 0; nf < 8; nf++)
        #pragma unroll
        for (int r = 0; r < 4; r++) yacc[nf][r] = 0.f;
    float m0 = -1e30f, m1 = -1e30f, l0 = 0.f, l1 = 0.f;

    const int arow0 = qb * 128 + r0;
    const int arow1 = arow0 + 8;
    const int ntiles = 2 * qb + 2;

    for (int t = 0; t < ntiles; t++) {
        const int s0k = t * 64;
        // ---- stage K (rope, tf32) ----
        for (int i = tid; i < 64 * 32; i += 256) {
            int row = i >> 5, j = i & 31;
            int n = s0k + row;
            const float* kr = Kg + (size_t)n * KVDIM + kvh * HD;
            float x0 = kr[j], x1 = kr[j + 32];
            float c0 = cosd[n * HD + j],      s0 = sind[n * HD + j];
            float c1 = cosd[n * HD + 32 + j], s1 = sind[n * HD + 32 + j];
            Ks[row * LDP + j]      = f2tf(x0 * c0 - x1 * s0);
            Ks[row * LDP + 32 + j] = f2tf(x1 * c1 + x0 * s1);
        }
        // ---- stage V transposed, packed key-pairs, hi/lo bf16 ----
        for (int i = tid; i < 64 * 32; i += 256) {
            int d = i & 63, kp = i >> 6;
            float v0 = Vg[(size_t)(s0k + 2*kp)     * KVDIM + kvh * HD + d];
            float v1 = Vg[(size_t)(s0k + 2*kp + 1) * KVDIM + kvh * HD + d];
            uint32_t hi, lo;
            split2(v0, v1, hi, lo);
            Vhi[d * LDV + kp] = hi;
            Vlo[d * LDV + kp] = lo;
        }
        __syncthreads();

        // ---- scores: S[16 x 64] per warp, tf32 ----
        float s[8][4];
        #pragma unroll
        for (int nf = 0; nf < 8; nf++)
            #pragma unroll
            for (int r = 0; r < 4; r++) s[nf][r] = 0.f;

        #pragma unroll
        for (int ki = 0; ki < 8; ki++) {
            const int c = ki * 8 + qz;
            uint32_t a[4];
            a[0] = Qs[r0 * LDP + c];
            a[1] = Qs[(r0 + 8) * LDP + c];
            a[2] = Qs[r0 * LDP + c + 4];
            a[3] = Qs[(r0 + 8) * LDP + c + 4];
            #pragma unroll
            for (int nf = 0; nf < 8; nf++) {
                const int krow = nf * 8 + (lane >> 2);
                uint32_t b[2];
                b[0] = Ks[krow * LDP + c];
                b[1] = Ks[krow * LDP + c + 4];
                mma_tf32(s[nf], a, b);
            }
        }

        // ---- causal mask ----
        if (s0k + 63 > qb * 128 + wrow) {
            #pragma unroll
            for (int nf = 0; nf < 8; nf++) {
                int key = s0k + nf * 8 + 2 * qz;
                if (key     > arow0) s[nf][0] = -1e30f;
                if (key + 1 > arow0) s[nf][1] = -1e30f;
                if (key     > arow1) s[nf][2] = -1e30f;
                if (key + 1 > arow1) s[nf][3] = -1e30f;
            }
        }

        // ---- online softmax ----
        float t0 = -1e30f, t1 = -1e30f;
        #pragma unroll
        for (int nf = 0; nf < 8; nf++) {
            t0 = fmaxf(t0, fmaxf(s[nf][0], s[nf][1]));
            t1 = fmaxf(t1, fmaxf(s[nf][2], s[nf][3]));
        }
        t0 = fmaxf(t0, __shfl_xor_sync(0xffffffff, t0, 1));
        t0 = fmaxf(t0, __shfl_xor_sync(0xffffffff, t0, 2));
        t1 = fmaxf(t1, __shfl_xor_sync(0xffffffff, t1, 1));
        t1 = fmaxf(t1, __shfl_xor_sync(0xffffffff, t1, 2));
        float nm0 = fmaxf(m0, t0), nm1 = fmaxf(m1, t1);
        float cor0 = __expf(m0 - nm0), cor1 = __expf(m1 - nm1);
        m0 = nm0; m1 = nm1;

        float ls0 = 0.f, ls1 = 0.f;
        #pragma unroll
        for (int nf = 0; nf < 8; nf++) {
            s[nf][0] = __expf(s[nf][0] - m0);
            s[nf][1] = __expf(s[nf][1] - m0);
            s[nf][2] = __expf(s[nf][2] - m1);
            s[nf][3] = __expf(s[nf][3] - m1);
            ls0 += s[nf][0] + s[nf][1];
            ls1 += s[nf][2] + s[nf][3];
        }
        ls0 += __shfl_xor_sync(0xffffffff, ls0, 1);
        ls0 += __shfl_xor_sync(0xffffffff, ls0, 2);
        ls1 += __shfl_xor_sync(0xffffffff, ls1, 1);
        ls1 += __shfl_xor_sync(0xffffffff, ls1, 2);
        l0 = l0 * cor0 + ls0;
        l1 = l1 * cor1 + ls1;
        #pragma unroll
        for (int nf = 0; nf < 8; nf++) {
            yacc[nf][0] *= cor0; yacc[nf][1] *= cor0;
            yacc[nf][2] *= cor1; yacc[nf][3] *= cor1;
        }

        // ---- PV: 3xbf16, P c-frag layout == a-frag layout (no transpose) ----
        #pragma unroll
        for (int ko = 0; ko < 4; ko++) {
            uint32_t ah[4], al[4];
            split2(s[2*ko][0],     s[2*ko][1],     ah[0], al[0]);  // row r0,   keys 16ko+2qz..+1
            split2(s[2*ko][2],     s[2*ko][3],     ah[1], al[1]);  // row r0+8
            split2(s[2*ko + 1][0], s[2*ko + 1][1], ah[2], al[2]);  // row r0,   keys +8
            split2(s[2*ko + 1][2], s[2*ko + 1][3], ah[3], al[3]);  // row r0+8, keys +8
            #pragma unroll
            for (int nf = 0; nf < 8; nf++) {
                const int d = nf * 8 + (lane >> 2);
                uint32_t bh[2], bl[2];
                bh[0] = Vhi[d * LDV + ko * 8 + qz];
                bh[1] = Vhi[d * LDV + ko * 8 + qz + 4];
                bl[0] = Vlo[d * LDV + ko * 8 + qz];
                bl[1] = Vlo[d * LDV + ko * 8 + qz + 4];
                mma_bf16(yacc[nf], ah, bh);
                mma_bf16(yacc[nf], al, bh);
                mma_bf16(yacc[nf], ah, bl);
            }
        }
        __syncthreads();
    }

    // ---- epilogue ----
    float i0 = 1.f / l0, i1 = 1.f / l1;
    #pragma unroll
    for (int nf = 0; nf < 8; nf++) {
        int col = h * HD + nf * 8 + 2 * qz;
        *(float2*)&Yg[(size_t)arow0 * DIM + col] =
            make_float2(yacc[nf][0] * i0, yacc[nf][1] * i0);
        *(float2*)&Yg[(size_t)arow1 * DIM + col] =
            make_float2(yacc[nf][2] * i1, yacc[nf][3] * i1);
    }
}

// ---------------- launch ----------------
extern "C" void kernel_launch(void* const* d_in, const int* in_sizes, int n_in,
                              void* d_out, int out_size)
{
    const float* x   = (const float*)d_in[0];
    const float* Wq  = (const float*)d_in[1];
    const float* Wk  = (const float*)d_in[2];
    const float* Wv  = (const float*)d_in[3];
    const float* Wo  = (const float*)d_in[4];
    const float* cosd= (const float*)d_in[5];
    const float* sind= (const float*)d_in[6];
    float* out = (float*)d_out;

    float *qp, *kp, *vp, *yp;
    cudaGetSymbolAddress((void**)&qp, g_q);
    cudaGetSymbolAddress((void**)&kp, g_k);
    cudaGetSymbolAddress((void**)&vp, g_v);
    cudaGetSymbolAddress((void**)&yp, g_y);

    constexpr int SMEM_128 = 4 * 128 * 20 * 4;                          // 40960 B
    constexpr int SMEM_64  = 4 * 64  * 20 * 4;                          // 20480 B
    constexpr int SMEM_ATTN = (128 * LDP + 64 * LDP + 2 * 64 * LDV) * 4; // 70656 B
    cudaFuncSetAttribute(gemm_bf16<128,128>,
                         cudaFuncAttributeMaxDynamicSharedMemorySize, SMEM_128);
    cudaFuncSetAttribute(gemm_bf16<64,64>,
                         cudaFuncAttributeMaxDynamicSharedMemorySize, SMEM_64);
    cudaFuncSetAttribute(attn_mma,
                         cudaFuncAttributeMaxDynamicSharedMemorySize, SMEM_ATTN);

    // 1,2: K,V projections
    gemm_bf16<64,64><<<dim3(KVDIM/64, NSEQ/64), 64, SMEM_64>>>(x, Wk, kp, NSEQ, KVDIM, DIM, 0);
    gemm_bf16<64,64><<<dim3(KVDIM/64, NSEQ/64), 64, SMEM_64>>>(x, Wv, vp, NSEQ, KVDIM, DIM, 0);
    // 3: Q projection
    gemm_bf16<128,128><<<dim3(DIM/128, NSEQ/128), 256, SMEM_128>>>(x, Wq, qp, NSEQ, DIM, DIM, 0);
    // 4: fused rope + flash attention  (profiled slot #4)
    attn_mma<<<dim3(16, HEADS), 256, SMEM_ATTN>>>(qp, kp, vp, cosd, sind, yp);
    // 5: output projection
    gemm_bf16<128,128><<<dim3(DIM/128, NSEQ/128), 256, SMEM_128>>>(yp, Wo, out, NSEQ, DIM, DIM, 0);
}

// round 6
// speedup vs baseline: 3.0827x; 1.0944x over previous
#include <cuda_runtime.h>
#include <cuda_bf16.h>
#include <math.h>
#include <stdint.h>

// Problem constants
#define NSEQ 2048
#define DIM  2048
#define HEADS 32
#define KVHEADS 4
#define HD 64
#define KVDIM (KVHEADS*HD)   // 256
#define REP (HEADS/KVHEADS)  // 8

// ---------------- scratch ----------------
__device__ float g_q[NSEQ * DIM];
__device__ float g_k[NSEQ * KVDIM];
__device__ float g_v[NSEQ * KVDIM];
__device__ float g_y[NSEQ * DIM];

// ---------------- helpers ----------------
__device__ __forceinline__ uint32_t f2tf(float x) {
    uint32_t r;
    asm("cvt.rna.tf32.f32 %0, %1;" : "=r"(r) : "f"(x));
    return r;
}

__device__ __forceinline__ float ex2(float x) {
    float r;
    asm("ex2.approx.f32 %0, %1;" : "=f"(r) : "f"(x));
    return r;
}

__device__ __forceinline__ uint32_t pkbf(float x0, float x1) {
    __nv_bfloat162 h = __floats2bfloat162_rn(x0, x1);
    return *reinterpret_cast<uint32_t*>(&h);
}

__device__ __forceinline__ void split2(float x0, float x1, uint32_t& hi, uint32_t& lo) {
    float h0 = __bfloat162float(__float2bfloat16(x0));
    float h1 = __bfloat162float(__float2bfloat16(x1));
    hi = pkbf(h0, h1);
    lo = pkbf(x0 - h0, x1 - h1);
}

__device__ __forceinline__ void mma_tf32(float* d, const uint32_t* a, const uint32_t* b) {
    asm volatile(
        "mma.sync.aligned.m16n8k8.row.col.f32.tf32.tf32.f32 "
        "{%0,%1,%2,%3}, {%4,%5,%6,%7}, {%8,%9}, {%0,%1,%2,%3};"
        : "+f"(d[0]), "+f"(d[1]), "+f"(d[2]), "+f"(d[3])
        : "r"(a[0]), "r"(a[1]), "r"(a[2]), "r"(a[3]), "r"(b[0]), "r"(b[1]));
}

__device__ __forceinline__ void mma_bf16(float* d, const uint32_t* a, const uint32_t* b) {
    asm volatile(
        "mma.sync.aligned.m16n8k16.row.col.f32.bf16.bf16.f32 "
        "{%0,%1,%2,%3}, {%4,%5,%6,%7}, {%8,%9}, {%0,%1,%2,%3};"
        : "+f"(d[0]), "+f"(d[1]), "+f"(d[2]), "+f"(d[3])
        : "r"(a[0]), "r"(a[1]), "r"(a[2]), "r"(a[3]), "r"(b[0]), "r"(b[1]));
}

// ---------------- 3xBF16 NT GEMM ----------------
// C[m][n] = sum_k A[m][k]*B[n][k]. BM=128, BN=64, 256 threads.
// 8 warps, warp-tile 32x32 (2 m-frags x 4 n-frags of m16n8k16).
// 2 CTAs/SM (regs<=128). blockIdx.z selects (B,C) vs (B2,C2) for fused K/V.
__global__ void __launch_bounds__(256, 2)
gemm_bf16(const float* __restrict__ A, const float* __restrict__ Bp,
          float* __restrict__ Cp, const float* __restrict__ B2,
          float* __restrict__ C2, int M, int N, int K)
{
    constexpr int BM = 128, BN = 64, BK = 32;
    constexpr int LDSW = BK/2 + 4;   // 20 u32 per row
    constexpr int THREADS = 256;
    constexpr int SA = BM * LDSW;
    constexpr int SB = BN * LDSW;
    constexpr int A4T = BM * (BK/4) / THREADS;  // 4
    constexpr int B4T = BN * (BK/4) / THREADS;  // 2

    const float* B = blockIdx.z ? B2 : Bp;
    float*       C = blockIdx.z ? C2 : Cp;

    extern __shared__ uint32_t sm[];
    uint32_t* Ah = sm;
    uint32_t* Al = sm + SA;
    uint32_t* Bh = sm + 2 * SA;
    uint32_t* Bl = sm + 2 * SA + SB;

    const int tid  = threadIdx.x;
    const int lane = tid & 31;
    const int warp = tid >> 5;
    const int wm   = warp >> 1;       // 0..3
    const int wn   = warp & 1;        // 0..1
    const int m0   = blockIdx.y * BM;
    const int n0   = blockIdx.x * BN;
    const int qz   = lane & 3;

    float acc[2][4][4];
    #pragma unroll
    for (int i = 0; i < 2; i++)
        #pragma unroll
        for (int j = 0; j < 4; j++)
            #pragma unroll
            for (int r = 0; r < 4; r++) acc[i][j][r] = 0.f;

    float4 pa[A4T], pb[B4T];
    #pragma unroll
    for (int i = 0; i < A4T; i++) {
        int idx = tid + i * THREADS;
        int row = idx / (BK/4), kq = (idx % (BK/4)) * 4;
        pa[i] = *(const float4*)&A[(size_t)(m0 + row) * K + kq];
    }
    #pragma unroll
    for (int i = 0; i < B4T; i++) {
        int idx = tid + i * THREADS;
        int row = idx / (BK/4), kq = (idx % (BK/4)) * 4;
        pb[i] = *(const float4*)&B[(size_t)(n0 + row) * K + kq];
    }

    for (int k0 = 0; k0 < K; k0 += BK) {
        #pragma unroll
        for (int i = 0; i < A4T; i++) {
            int idx = tid + i * THREADS;
            int row = idx / (BK/4), kq = (idx % (BK/4)) * 4;
            uint32_t h01, l01, h23, l23;
            split2(pa[i].x, pa[i].y, h01, l01);
            split2(pa[i].z, pa[i].w, h23, l23);
            Ah[row * LDSW + kq/2]     = h01;
            Ah[row * LDSW + kq/2 + 1] = h23;
            Al[row * LDSW + kq/2]     = l01;
            Al[row * LDSW + kq/2 + 1] = l23;
        }
        #pragma unroll
        for (int i = 0; i < B4T; i++) {
            int idx = tid + i * THREADS;
            int row = idx / (BK/4), kq = (idx % (BK/4)) * 4;
            uint32_t h01, l01, h23, l23;
            split2(pb[i].x, pb[i].y, h01, l01);
            split2(pb[i].z, pb[i].w, h23, l23);
            Bh[row * LDSW + kq/2]     = h01;
            Bh[row * LDSW + kq/2 + 1] = h23;
            Bl[row * LDSW + kq/2]     = l01;
            Bl[row * LDSW + kq/2 + 1] = l23;
        }
        __syncthreads();

        if (k0 + BK < K) {
            #pragma unroll
            for (int i = 0; i < A4T; i++) {
                int idx = tid + i * THREADS;
                int row = idx / (BK/4), kq = (idx % (BK/4)) * 4;
                pa[i] = *(const float4*)&A[(size_t)(m0 + row) * K + k0 + BK + kq];
            }
            #pragma unroll
            for (int i = 0; i < B4T; i++) {
                int idx = tid + i * THREADS;
                int row = idx / (BK/4), kq = (idx % (BK/4)) * 4;
                pb[i] = *(const float4*)&B[(size_t)(n0 + row) * K + k0 + BK + kq];
            }
        }

        #pragma unroll
        for (int ks = 0; ks < 2; ks++) {
            const int c0 = ks * 8 + qz;
            uint32_t ah[2][4], al[2][4], bh[4][2], bl[4][2];
            #pragma unroll
            for (int i = 0; i < 2; i++) {
                int r0 = wm * 32 + i * 16 + (lane >> 2);
                ah[i][0] = Ah[r0 * LDSW + c0];
                ah[i][1] = Ah[(r0 + 8) * LDSW + c0];
                ah[i][2] = Ah[r0 * LDSW + c0 + 4];
                ah[i][3] = Ah[(r0 + 8) * LDSW + c0 + 4];
                al[i][0] = Al[r0 * LDSW + c0];
                al[i][1] = Al[(r0 + 8) * LDSW + c0];
                al[i][2] = Al[r0 * LDSW + c0 + 4];
                al[i][3] = Al[(r0 + 8) * LDSW + c0 + 4];
            }
            #pragma unroll
            for (int j = 0; j < 4; j++) {
                int nr = wn * 32 + j * 8 + (lane >> 2);
                bh[j][0] = Bh[nr * LDSW + c0];
                bh[j][1] = Bh[nr * LDSW + c0 + 4];
                bl[j][0] = Bl[nr * LDSW + c0];
                bl[j][1] = Bl[nr * LDSW + c0 + 4];
            }
            #pragma unroll
            for (int i = 0; i < 2; i++)
                #pragma unroll
                for (int j = 0; j < 4; j++) {
                    mma_bf16(acc[i][j], ah[i], bh[j]);
                    mma_bf16(acc[i][j], al[i], bh[j]);
                    mma_bf16(acc[i][j], ah[i], bl[j]);
                }
        }
        __syncthreads();
    }

    #pragma unroll
    for (int i = 0; i < 2; i++) {
        #pragma unroll
        for (int j = 0; j < 4; j++) {
            int row = m0 + wm * 32 + i * 16 + (lane >> 2);
            int col = n0 + wn * 32 + j * 8 + qz * 2;
            *(float2*)&C[(size_t)row * N + col]       = make_float2(acc[i][j][0], acc[i][j][1]);
            *(float2*)&C[(size_t)(row + 8) * N + col] = make_float2(acc[i][j][2], acc[i][j][3]);
        }
    }
}

// ---------------- MMA flash attention (RoPE fused, causal) ----------------
// CTA: 128 q-rows x 1 head, 256 threads (8 warps x 16 rows). 64-key tiles.
// Scores: single tf32 (scale*log2e folded into Q). PV: 3xbf16.
#define LDP 68
#define LDV 36
#define SCL2E 0.18033688f   // 0.125 * log2(e)

__global__ void __launch_bounds__(256, 2)
attn_mma(const float* __restrict__ Qg, const float* __restrict__ Kg,
         const float* __restrict__ Vg, const float* __restrict__ cosd,
         const float* __restrict__ sind, float* __restrict__ Yg)
{
    extern __shared__ uint32_t sm[];
    uint32_t* Qs  = sm;                  // [128][LDP] tf32
    uint32_t* Ks  = Qs  + 128 * LDP;     // [64][LDP]  tf32
    uint32_t* Vhi = Ks  + 64 * LDP;      // [64 d][LDV kp] packed bf16x2
    uint32_t* Vlo = Vhi + 64 * LDV;

    const int tid  = threadIdx.x;
    const int lane = tid & 31;
    const int warp = tid >> 5;
    const int qb   = (gridDim.x - 1) - blockIdx.x;
    const int h    = blockIdx.y;
    const int kvh  = h >> 3;
    const int wrow = warp * 16;
    const int r0   = wrow + (lane >> 2);
    const int qz   = lane & 3;

    // ---- stage Q: rope + scale*log2e, tf32 ----
    for (int i = tid; i < 128 * 32; i += 256) {
        int row = i >> 5, j = i & 31;
        int n = qb * 128 + row;
        const float* qr = Qg + (size_t)n * DIM + h * HD;
        float x0 = qr[j], x1 = qr[j + 32];
        float c0 = cosd[n * HD + j],      s0 = sind[n * HD + j];
        float c1 = cosd[n * HD + 32 + j], s1 = sind[n * HD + 32 + j];
        Qs[row * LDP + j]      = f2tf((x0 * c0 - x1 * s0) * SCL2E);
        Qs[row * LDP + 32 + j] = f2tf((x1 * c1 + x0 * s1) * SCL2E);
    }

    float yacc[8][4];
    #pragma unroll
    for (int nf = 0; nf < 8; nf++)
        #pragma unroll
        for (int r = 0; r < 4; r++) yacc[nf][r] = 0.f;
    float m0 = -1e30f, m1 = -1e30f, l0 = 0.f, l1 = 0.f;

    const int arow0 = qb * 128 + r0;
    const int arow1 = arow0 + 8;
    const int ntiles = 2 * qb + 2;

    for (int t = 0; t < ntiles; t++) {
        const int s0k = t * 64;
        for (int i = tid; i < 64 * 32; i += 256) {
            int row = i >> 5, j = i & 31;
            int n = s0k + row;
            const float* kr = Kg + (size_t)n * KVDIM + kvh * HD;
            float x0 = kr[j], x1 = kr[j + 32];
            float c0 = cosd[n * HD + j],      s0 = sind[n * HD + j];
            float c1 = cosd[n * HD + 32 + j], s1 = sind[n * HD + 32 + j];
            Ks[row * LDP + j]      = f2tf(x0 * c0 - x1 * s0);
            Ks[row * LDP + 32 + j] = f2tf(x1 * c1 + x0 * s1);
        }
        for (int i = tid; i < 64 * 32; i += 256) {
            int d = i & 63, kp = i >> 6;
            float v0 = Vg[(size_t)(s0k + 2*kp)     * KVDIM + kvh * HD + d];
            float v1 = Vg[(size_t)(s0k + 2*kp + 1) * KVDIM + kvh * HD + d];
            uint32_t hi, lo;
            split2(v0, v1, hi, lo);
            Vhi[d * LDV + kp] = hi;
            Vlo[d * LDV + kp] = lo;
        }
        __syncthreads();

        float s[8][4];
        #pragma unroll
        for (int nf = 0; nf < 8; nf++)
            #pragma unroll
            for (int r = 0; r < 4; r++) s[nf][r] = 0.f;

        #pragma unroll
        for (int ki = 0; ki < 8; ki++) {
            const int c = ki * 8 + qz;
            uint32_t a[4];
            a[0] = Qs[r0 * LDP + c];
            a[1] = Qs[(r0 + 8) * LDP + c];
            a[2] = Qs[r0 * LDP + c + 4];
            a[3] = Qs[(r0 + 8) * LDP + c + 4];
            #pragma unroll
            for (int nf = 0; nf < 8; nf++) {
                const int krow = nf * 8 + (lane >> 2);
                uint32_t b[2];
                b[0] = Ks[krow * LDP + c];
                b[1] = Ks[krow * LDP + c + 4];
                mma_tf32(s[nf], a, b);
            }
        }

        if (s0k + 63 > qb * 128 + wrow) {
            #pragma unroll
            for (int nf = 0; nf < 8; nf++) {
                int key = s0k + nf * 8 + 2 * qz;
                if (key     > arow0) s[nf][0] = -1e30f;
                if (key + 1 > arow0) s[nf][1] = -1e30f;
                if (key     > arow1) s[nf][2] = -1e30f;
                if (key + 1 > arow1) s[nf][3] = -1e30f;
            }
        }

        float t0 = -1e30f, t1 = -1e30f;
        #pragma unroll
        for (int nf = 0; nf < 8; nf++) {
            t0 = fmaxf(t0, fmaxf(s[nf][0], s[nf][1]));
            t1 = fmaxf(t1, fmaxf(s[nf][2], s[nf][3]));
        }
        t0 = fmaxf(t0, __shfl_xor_sync(0xffffffff, t0, 1));
        t0 = fmaxf(t0, __shfl_xor_sync(0xffffffff, t0, 2));
        t1 = fmaxf(t1, __shfl_xor_sync(0xffffffff, t1, 1));
        t1 = fmaxf(t1, __shfl_xor_sync(0xffffffff, t1, 2));
        float nm0 = fmaxf(m0, t0), nm1 = fmaxf(m1, t1);
        float cor0 = ex2(m0 - nm0), cor1 = ex2(m1 - nm1);
        m0 = nm0; m1 = nm1;

        float ls0 = 0.f, ls1 = 0.f;
        #pragma unroll
        for (int nf = 0; nf < 8; nf++) {
            s[nf][0] = ex2(s[nf][0] - m0);
            s[nf][1] = ex2(s[nf][1] - m0);
            s[nf][2] = ex2(s[nf][2] - m1);
            s[nf][3] = ex2(s[nf][3] - m1);
            ls0 += s[nf][0] + s[nf][1];
            ls1 += s[nf][2] + s[nf][3];
        }
        ls0 += __shfl_xor_sync(0xffffffff, ls0, 1);
        ls0 += __shfl_xor_sync(0xffffffff, ls0, 2);
        ls1 += __shfl_xor_sync(0xffffffff, ls1, 1);
        ls1 += __shfl_xor_sync(0xffffffff, ls1, 2);
        l0 = l0 * cor0 + ls0;
        l1 = l1 * cor1 + ls1;
        #pragma unroll
        for (int nf = 0; nf < 8; nf++) {
            yacc[nf][0] *= cor0; yacc[nf][1] *= cor0;
            yacc[nf][2] *= cor1; yacc[nf][3] *= cor1;
        }

        #pragma unroll
        for (int ko = 0; ko < 4; ko++) {
            uint32_t ah[4], al[4];
            split2(s[2*ko][0],     s[2*ko][1],     ah[0], al[0]);
            split2(s[2*ko][2],     s[2*ko][3],     ah[1], al[1]);
            split2(s[2*ko + 1][0], s[2*ko + 1][1], ah[2], al[2]);
            split2(s[2*ko + 1][2], s[2*ko + 1][3], ah[3], al[3]);
            #pragma unroll
            for (int nf = 0; nf < 8; nf++) {
                const int d = nf * 8 + (lane >> 2);
                uint32_t bh[2], bl[2];
                bh[0] = Vhi[d * LDV + ko * 8 + qz];
                bh[1] = Vhi[d * LDV + ko * 8 + qz + 4];
                bl[0] = Vlo[d * LDV + ko * 8 + qz];
                bl[1] = Vlo[d * LDV + ko * 8 + qz + 4];
                mma_bf16(yacc[nf], ah, bh);
                mma_bf16(yacc[nf], al, bh);
                mma_bf16(yacc[nf], ah, bl);
            }
        }
        __syncthreads();
    }

    float i0 = 1.f / l0, i1 = 1.f / l1;
    #pragma unroll
    for (int nf = 0; nf < 8; nf++) {
        int col = h * HD + nf * 8 + 2 * qz;
        *(float2*)&Yg[(size_t)arow0 * DIM + col] =
            make_float2(yacc[nf][0] * i0, yacc[nf][1] * i0);
        *(float2*)&Yg[(size_t)arow1 * DIM + col] =
            make_float2(yacc[nf][2] * i1, yacc[nf][3] * i1);
    }
}

// ---------------- launch ----------------
extern "C" void kernel_launch(void* const* d_in, const int* in_sizes, int n_in,
                              void* d_out, int out_size)
{
    const float* x   = (const float*)d_in[0];
    const float* Wq  = (const float*)d_in[1];
    const float* Wk  = (const float*)d_in[2];
    const float* Wv  = (const float*)d_in[3];
    const float* Wo  = (const float*)d_in[4];
    const float* cosd= (const float*)d_in[5];
    const float* sind= (const float*)d_in[6];
    float* out = (float*)d_out;

    float *qp, *kp, *vp, *yp;
    cudaGetSymbolAddress((void**)&qp, g_q);
    cudaGetSymbolAddress((void**)&kp, g_k);
    cudaGetSymbolAddress((void**)&vp, g_v);
    cudaGetSymbolAddress((void**)&yp, g_y);

    constexpr int SMEM_G = (128 + 64) * 20 * 2 * 4;                      // 30720 B
    constexpr int SMEM_ATTN = (128 * LDP + 64 * LDP + 2 * 64 * LDV) * 4; // 70656 B
    cudaFuncSetAttribute(attn_mma,
                         cudaFuncAttributeMaxDynamicSharedMemorySize, SMEM_ATTN);

    // 1: fused K+V projections (z=0 -> K, z=1 -> V)
    gemm_bf16<<<dim3(KVDIM/64, NSEQ/128, 2), 256, SMEM_G>>>(x, Wk, kp, Wv, vp, NSEQ, KVDIM, DIM);
    // 2: Q projection
    gemm_bf16<<<dim3(DIM/64, NSEQ/128, 1), 256, SMEM_G>>>(x, Wq, qp, Wq, qp, NSEQ, DIM, DIM);
    // 3: fused rope + flash attention
    attn_mma<<<dim3(16, HEADS), 256, SMEM_ATTN>>>(qp, kp, vp, cosd, sind, yp);
    // 4: output projection (profiled slot #4)
    gemm_bf16<<<dim3(DIM/64, NSEQ/128, 1), 256, SMEM_G>>>(yp, Wo, out, Wo, out, NSEQ, DIM, DIM);
}